// round 10
// baseline (speedup 1.0000x reference)
#include <cuda_runtime.h>
#include <cuda_fp16.h>

#define NN 100000
#define EE 1600000
#define GG 2048
#define HD 64
#define SCAN_B 1024
#define SCAN_G ((NN + SCAN_B - 1) / SCAN_B)   // 98

// ---------------- scratch ----------------
__device__ float    g_hA[NN * HD];
__device__ __half   g_hw[NN * HD];
__device__ float    g_dinv[NN];
__device__ float    g_as[NN], g_ad[NN];
__device__ int      g_cnt[NN];          // stays zeroed between runs
__device__ int      g_rs[NN + 1];
__device__ int      g_cur[NN];
__device__ int      g_bsum[SCAN_G], g_boff[SCAN_G];
__device__ int      g_tick;             // stays zeroed between runs
__device__ unsigned g_es[EE];           // edge-ordered half2(es1,es2)
__device__ uint2    c_pack[EE];         // (src, half2(es1,es2)) CSR-ordered
__device__ unsigned g_pool[GG * HD];    // re-armed by k_fc each run
__device__ float    g_v[32];

__device__ __forceinline__ unsigned encf(float f) {
    unsigned u = __float_as_uint(f);
    return (u & 0x80000000u) ? ~u : (u | 0x80000000u);
}
__device__ __forceinline__ float decf(unsigned u) {
    return __uint_as_float((u & 0x80000000u) ? (u & 0x7fffffffu) : ~u);
}
#define ENC_NEGINF 0x007fffffu

__device__ __forceinline__ float lrelu(float a) { return (a > 0.f) ? a : 0.2f * a; }

// ---------------- setup ----------------

__global__ void k_vecs(const float* __restrict__ We1, const float* __restrict__ ae1,
                       const float* __restrict__ We2, const float* __restrict__ ae2) {
    int t = threadIdx.x;
    if (t >= 32) return;
    const float* We = (t < 16) ? We1 : We2;
    const float* ae = (t < 16) ? ae1 : ae2;
    int j = t & 15;
    float s = 0.f;
    #pragma unroll 8
    for (int c = 0; c < HD; c++) s += We[j * HD + c] * ae[c];
    g_v[t] = s;
}

// degree count + es dot-products (2 edges/thread, split halves, coalesced)
__global__ void k_cnt(const float* __restrict__ ea, const int* __restrict__ dst) {
    int i = blockIdx.x * blockDim.x + threadIdx.x;
    if (i >= EE / 2) return;
    int i2 = i + EE / 2;
    const float4* pA = (const float4*)(ea + (size_t)i  * 16);
    const float4* pB = (const float4*)(ea + (size_t)i2 * 16);
    float4 qa0 = pA[0], qa1 = pA[1], qa2 = pA[2], qa3 = pA[3];
    float4 qb0 = pB[0], qb1 = pB[1], qb2 = pB[2], qb3 = pB[3];
    int dA = dst[i], dB = dst[i2];
    float ea_[16], eb_[16];
    ea_[0]=qa0.x; ea_[1]=qa0.y; ea_[2]=qa0.z; ea_[3]=qa0.w;
    ea_[4]=qa1.x; ea_[5]=qa1.y; ea_[6]=qa1.z; ea_[7]=qa1.w;
    ea_[8]=qa2.x; ea_[9]=qa2.y; ea_[10]=qa2.z; ea_[11]=qa2.w;
    ea_[12]=qa3.x; ea_[13]=qa3.y; ea_[14]=qa3.z; ea_[15]=qa3.w;
    eb_[0]=qb0.x; eb_[1]=qb0.y; eb_[2]=qb0.z; eb_[3]=qb0.w;
    eb_[4]=qb1.x; eb_[5]=qb1.y; eb_[6]=qb1.z; eb_[7]=qb1.w;
    eb_[8]=qb2.x; eb_[9]=qb2.y; eb_[10]=qb2.z; eb_[11]=qb2.w;
    eb_[12]=qb3.x; eb_[13]=qb3.y; eb_[14]=qb3.z; eb_[15]=qb3.w;
    float sA1 = 0.f, sA2 = 0.f, sB1 = 0.f, sB2 = 0.f;
    #pragma unroll
    for (int k = 0; k < 16; k++) {
        float v1 = g_v[k], v2 = g_v[16 + k];
        sA1 += ea_[k] * v1; sA2 += ea_[k] * v2;
        sB1 += eb_[k] * v1; sB2 += eb_[k] * v2;
    }
    __half2 hA = __floats2half2_rn(sA1, sA2);
    __half2 hB = __floats2half2_rn(sB1, sB2);
    g_es[i]  = *reinterpret_cast<unsigned*>(&hA);
    g_es[i2] = *reinterpret_cast<unsigned*>(&hB);
    atomicAdd(&g_cnt[dA], 1);
    atomicAdd(&g_cnt[dB], 1);
}

__global__ void k_scan1() {
    __shared__ int sh[SCAN_B];
    __shared__ int is_last;
    int t = threadIdx.x;
    int i = blockIdx.x * SCAN_B + t;
    int v = (i < NN) ? g_cnt[i] : 0;
    sh[t] = v;
    __syncthreads();
    for (int off = 1; off < SCAN_B; off <<= 1) {
        int x = (t >= off) ? sh[t - off] : 0;
        __syncthreads();
        sh[t] += x;
        __syncthreads();
    }
    if (i < NN) g_rs[i] = sh[t] - v;
    if (t == SCAN_B - 1) g_bsum[blockIdx.x] = sh[t];
    __threadfence();
    __syncthreads();
    if (t == 0) is_last = (atomicAdd(&g_tick, 1) == SCAN_G - 1) ? 1 : 0;
    __syncthreads();
    if (is_last) __threadfence();
    if (is_last && t < 32) {
        int lane = t;
        int base = lane * 4;
        int v0 = (base + 0 < SCAN_G) ? g_bsum[base + 0] : 0;
        int v1 = (base + 1 < SCAN_G) ? g_bsum[base + 1] : 0;
        int v2 = (base + 2 < SCAN_G) ? g_bsum[base + 2] : 0;
        int v3 = (base + 3 < SCAN_G) ? g_bsum[base + 3] : 0;
        int e1 = v0, e2 = v0 + v1, e3 = v0 + v1 + v2;
        int tot = e3 + v3;
        int x = tot;
        #pragma unroll
        for (int off = 1; off < 32; off <<= 1) {
            int y = __shfl_up_sync(0xffffffffu, x, off);
            if (lane >= off) x += y;
        }
        int excl = x - tot;
        if (base + 0 < SCAN_G) g_boff[base + 0] = excl;
        if (base + 1 < SCAN_G) g_boff[base + 1] = excl + e1;
        if (base + 2 < SCAN_G) g_boff[base + 2] = excl + e2;
        if (base + 3 < SCAN_G) g_boff[base + 3] = excl + e3;
        if (lane == 0) g_tick = 0;
    }
}

__global__ void k_scan3() {
    int i = blockIdx.x * SCAN_B + threadIdx.x;
    if (i < NN) {
        int cv = g_cnt[i];
        g_cnt[i] = 0;
        int rs = g_rs[i] + g_boff[blockIdx.x];
        g_rs[i] = rs;
        g_cur[i] = rs;
        g_dinv[i] = rsqrtf((float)(cv + 1));
    }
    if (i == 0) g_rs[NN] = EE;
}

// pure permutation scatter: 4 edges/thread via int4/uint4 loads
__global__ void k_scatter(const int4* __restrict__ src4, const int4* __restrict__ dst4) {
    int i = blockIdx.x * blockDim.x + threadIdx.x;
    if (i >= EE / 4) return;
    int4 s = src4[i];
    int4 d = dst4[i];
    uint4 e = ((const uint4*)g_es)[i];
    int p0 = atomicAdd(&g_cur[d.x], 1);
    int p1 = atomicAdd(&g_cur[d.y], 1);
    int p2 = atomicAdd(&g_cur[d.z], 1);
    int p3 = atomicAdd(&g_cur[d.w], 1);
    c_pack[p0] = make_uint2((unsigned)s.x, e.x);
    c_pack[p1] = make_uint2((unsigned)s.y, e.y);
    c_pack[p2] = make_uint2((unsigned)s.z, e.z);
    c_pack[p3] = make_uint2((unsigned)s.w, e.w);
}

// ---------------- tensor-core GEMM ----------------
template <int KD, int ATT>
__global__ void k_gemm(const float* __restrict__ Xext, const float* __restrict__ W,
                       const float* __restrict__ att_s, const float* __restrict__ att_d,
                       int useInternal) {
    const float* X = useInternal ? g_hA : Xext;
    __shared__ __half Xs[64][KD + 8];
    __shared__ __half Ws[KD][72];
    __shared__ float sred[64], dred[64];
    int tid = threadIdx.x;
    int node0 = blockIdx.x * 64;

    for (int i = tid; i < 64 * KD; i += 256) {
        int r = i / KD, k = i % KD;
        float v = (node0 + r < NN) ? X[(size_t)(node0 + r) * KD + k] : 0.f;
        Xs[r][k] = __float2half(v);
    }
    for (int i = tid; i < KD * 64; i += 256) {
        int k = i >> 6, n = i & 63;
        Ws[k][n] = __float2half(W[k * 64 + n]);
    }
    if (ATT && tid < 64) { sred[tid] = 0.f; dred[tid] = 0.f; }
    __syncthreads();

    int wid  = tid >> 5;
    int lane = tid & 31;
    int rt = wid >> 1;
    int ch = wid & 1;
    int g  = lane >> 2;
    int t2 = (lane & 3) * 2;
    int row0 = rt * 16;

    float c[4][4];
    #pragma unroll
    for (int nt = 0; nt < 4; nt++)
        #pragma unroll
        for (int q = 0; q < 4; q++) c[nt][q] = 0.f;

    #pragma unroll
    for (int ks = 0; ks < KD / 16; ks++) {
        int k0 = ks * 16;
        unsigned a0 = *(const unsigned*)&Xs[row0 + g    ][k0 + t2];
        unsigned a1 = *(const unsigned*)&Xs[row0 + g + 8][k0 + t2];
        unsigned a2 = *(const unsigned*)&Xs[row0 + g    ][k0 + t2 + 8];
        unsigned a3 = *(const unsigned*)&Xs[row0 + g + 8][k0 + t2 + 8];
        #pragma unroll
        for (int nt = 0; nt < 4; nt++) {
            int n0 = ch * 32 + nt * 8 + g;
            __half2 b0h = __halves2half2(Ws[k0 + t2    ][n0], Ws[k0 + t2 + 1][n0]);
            __half2 b1h = __halves2half2(Ws[k0 + t2 + 8][n0], Ws[k0 + t2 + 9][n0]);
            unsigned b0 = *reinterpret_cast<unsigned*>(&b0h);
            unsigned b1 = *reinterpret_cast<unsigned*>(&b1h);
            asm volatile(
                "mma.sync.aligned.m16n8k16.row.col.f32.f16.f16.f32 "
                "{%0,%1,%2,%3}, {%4,%5,%6,%7}, {%8,%9}, {%0,%1,%2,%3};"
                : "+f"(c[nt][0]), "+f"(c[nt][1]), "+f"(c[nt][2]), "+f"(c[nt][3])
                : "r"(a0), "r"(a1), "r"(a2), "r"(a3), "r"(b0), "r"(b1));
        }
    }

    int rowA = node0 + row0 + g;
    int rowB = rowA + 8;
    #pragma unroll
    for (int nt = 0; nt < 4; nt++) {
        int col = ch * 32 + nt * 8 + t2;
        if (rowA < NN)
            *(__half2*)&g_hw[(size_t)rowA * 64 + col] = __floats2half2_rn(c[nt][0], c[nt][1]);
        if (rowB < NN)
            *(__half2*)&g_hw[(size_t)rowB * 64 + col] = __floats2half2_rn(c[nt][2], c[nt][3]);
    }

    if (ATT) {
        float pAs = 0.f, pAd = 0.f, pBs = 0.f, pBd = 0.f;
        #pragma unroll
        for (int nt = 0; nt < 4; nt++) {
            int col = ch * 32 + nt * 8 + t2;
            float s0 = att_s[col], s1v = att_s[col + 1];
            float d0 = att_d[col], d1v = att_d[col + 1];
            pAs += c[nt][0] * s0 + c[nt][1] * s1v;
            pAd += c[nt][0] * d0 + c[nt][1] * d1v;
            pBs += c[nt][2] * s0 + c[nt][3] * s1v;
            pBd += c[nt][2] * d0 + c[nt][3] * d1v;
        }
        #pragma unroll
        for (int o = 1; o < 4; o <<= 1) {
            pAs += __shfl_xor_sync(0xffffffffu, pAs, o);
            pAd += __shfl_xor_sync(0xffffffffu, pAd, o);
            pBs += __shfl_xor_sync(0xffffffffu, pBs, o);
            pBd += __shfl_xor_sync(0xffffffffu, pBd, o);
        }
        if ((lane & 3) == 0) {
            atomicAdd(&sred[row0 + g],     pAs);
            atomicAdd(&dred[row0 + g],     pAd);
            atomicAdd(&sred[row0 + g + 8], pBs);
            atomicAdd(&dred[row0 + g + 8], pBd);
        }
        __syncthreads();
        if (tid < 64 && node0 + tid < NN) {
            g_as[node0 + tid] = sred[tid];
            g_ad[node0 + tid] = dred[tid];
        }
    }
}

// ---------------- gathers (R7 style, unroll 8) ----------------

__device__ __forceinline__ float2 hwrow(int s, int lane) {
    __half2 v = *((const __half2*)(g_hw + (size_t)s * 64) + lane);
    return __half22float2(v);
}

__global__ void k_gcn_node(const float* __restrict__ b) {
    int node = blockIdx.x * 8 + (threadIdx.x >> 5);
    int lane = threadIdx.x & 31;
    if (node >= NN) return;
    int rs = g_rs[node], re = g_rs[node + 1];
    float a0 = 0.f, a1 = 0.f;
    for (int jb = rs; jb < re; jb += 32) {
        int n = re - jb; if (n > 32) n = 32;
        int s_l = 0; float w_l = 0.f;
        if (lane < n) {
            s_l = (int)c_pack[jb + lane].x;
            w_l = g_dinv[s_l];
        }
        #pragma unroll 8
        for (int j = 0; j < n; j++) {
            int s   = __shfl_sync(0xffffffffu, s_l, j);
            float w = __shfl_sync(0xffffffffu, w_l, j);
            float2 f = hwrow(s, lane);
            a0 += w * f.x; a1 += w * f.y;
        }
    }
    float di = g_dinv[node];
    float2 fs = hwrow(node, lane);
    a0 += di * fs.x; a1 += di * fs.y;
    float2 bb = ((const float2*)b)[lane];
    float2 o;
    o.x = fmaxf(a0 * di + bb.x, 0.f);
    o.y = fmaxf(a1 * di + bb.y, 0.f);
    ((float2*)(g_hA + (size_t)node * 64))[lane] = o;
}

template <int LAYER>
__global__ void k_gat_node(const float* __restrict__ b) {
    int node = blockIdx.x * 8 + (threadIdx.x >> 5);
    int lane = threadIdx.x & 31;
    if (node >= NN) return;
    int rs = g_rs[node], re = g_rs[node + 1];
    float ad_n = g_ad[node];
    float a0 = 0.f, a1 = 0.f, den_l = 0.f, es_l = 0.f;
    for (int jb = rs; jb < re; jb += 32) {
        int n = re - jb; if (n > 32) n = 32;
        int s_l = 0; float x_l = 0.f;
        if (lane < n) {
            uint2 q = c_pack[jb + lane];
            s_l = (int)q.x;
            __half2 eh = *reinterpret_cast<__half2*>(&q.y);
            float e = (LAYER == 1) ? __low2float(eh) : __high2float(eh);
            x_l = __expf(lrelu(g_as[s_l] + ad_n + e));
            den_l += x_l;
            es_l  += e;
        }
        #pragma unroll 8
        for (int j = 0; j < n; j++) {
            int s   = __shfl_sync(0xffffffffu, s_l, j);
            float x = __shfl_sync(0xffffffffu, x_l, j);
            float2 f = hwrow(s, lane);
            a0 += x * f.x; a1 += x * f.y;
        }
    }
    #pragma unroll
    for (int o = 16; o; o >>= 1) {
        den_l += __shfl_xor_sync(0xffffffffu, den_l, o);
        es_l  += __shfl_xor_sync(0xffffffffu, es_l, o);
    }
    float cnt = (float)(re - rs);
    float x = __expf(lrelu(g_as[node] + ad_n + es_l / fmaxf(cnt, 1.f)));
    float den = den_l + x;
    float2 fs = hwrow(node, lane);
    a0 += x * fs.x; a1 += x * fs.y;
    float inv = 1.f / den;
    float2 bb = ((const float2*)b)[lane];
    float2 o;
    o.x = fmaxf(a0 * inv + bb.x, 0.f);
    o.y = fmaxf(a1 * inv + bb.y, 0.f);
    ((float2*)(g_hA + (size_t)node * 64))[lane] = o;
}

// ---------------- pool + head ----------------

__global__ void k_pool(const int* __restrict__ batch) {
    int c   = threadIdx.x & 63;
    int grp = threadIdx.x >> 6;
    int n0  = blockIdx.x * 64 + grp * 16;
    if (n0 >= NN) return;
    int curg = batch[n0];
    float m = -3.402823466e+38f;
    for (int k = 0; k < 16; k++) {
        int n = n0 + k;
        if (n >= NN) break;
        int bg = batch[n];
        if (bg != curg) {
            atomicMax(&g_pool[curg * 64 + c], encf(m));
            m = -3.402823466e+38f;
            curg = bg;
        }
        m = fmaxf(m, g_hA[(size_t)n * 64 + c]);
    }
    atomicMax(&g_pool[curg * 64 + c], encf(m));
}

__global__ void k_fc(const float* __restrict__ W1, const float* __restrict__ b1,
                     const float* __restrict__ W2, const float* __restrict__ b2,
                     float* __restrict__ out) {
    __shared__ float t0[64], t1[64];
    int g = blockIdx.x, c = threadIdx.x;
    t0[c] = decf(g_pool[g * 64 + c]);
    g_pool[g * 64 + c] = ENC_NEGINF;
    __syncthreads();
    float s = 0.f;
    #pragma unroll 8
    for (int k = 0; k < 64; k++) s += t0[k] * W1[k * 64 + c];
    t1[c] = fmaxf(s + b1[c], 0.f);
    __syncthreads();
    float o = 0.f;
    #pragma unroll 8
    for (int k = 0; k < 64; k++) o += t1[k] * W2[k * 64 + c];
    out[g * 64 + c] = o + b2[c];
}

// ---------------- launch ----------------
extern "C" void kernel_launch(void* const* d_in, const int* in_sizes, int n_in,
                              void* d_out, int out_size) {
    const float* x     = (const float*)d_in[0];
    const int*   ei    = (const int*)  d_in[1];
    const float* ea    = (const float*)d_in[2];
    const int*   batch = (const int*)  d_in[3];
    const float* W_gcn = (const float*)d_in[4];
    const float* b_gcn = (const float*)d_in[5];
    const float* W1    = (const float*)d_in[6];
    const float* We1   = (const float*)d_in[7];
    const float* as1   = (const float*)d_in[8];
    const float* ad1   = (const float*)d_in[9];
    const float* ae1   = (const float*)d_in[10];
    const float* b1    = (const float*)d_in[11];
    const float* W2    = (const float*)d_in[12];
    const float* We2   = (const float*)d_in[13];
    const float* as2   = (const float*)d_in[14];
    const float* ad2   = (const float*)d_in[15];
    const float* ae2   = (const float*)d_in[16];
    const float* b2    = (const float*)d_in[17];
    const float* Wf1   = (const float*)d_in[18];
    const float* bf1   = (const float*)d_in[19];
    const float* Wf2   = (const float*)d_in[20];
    const float* bf2   = (const float*)d_in[21];
    float* out = (float*)d_out;

    const int* src = ei;
    const int* dst = ei + EE;

    const int TB = 256;
    const int gGemm = (NN + 63) / 64;
    const int gNode = (NN + 7) / 8;

    cudaStream_t s2;
    cudaEvent_t evA, evB;
    cudaStreamCreateWithFlags(&s2, cudaStreamNonBlocking);
    cudaEventCreateWithFlags(&evA, cudaEventDisableTiming);
    cudaEventCreateWithFlags(&evB, cudaEventDisableTiming);

    cudaEventRecord(evA, 0);
    cudaStreamWaitEvent(s2, evA, 0);
    k_gemm<128, 0><<<gGemm, TB, 0, s2>>>(x, W_gcn, nullptr, nullptr, 0);
    cudaEventRecord(evB, s2);

    k_vecs<<<1, 32>>>(We1, ae1, We2, ae2);
    k_cnt<<<(EE / 2 + TB - 1) / TB, TB>>>(ea, dst);
    k_scan1<<<SCAN_G, SCAN_B>>>();
    k_scan3<<<SCAN_G, SCAN_B>>>();
    k_scatter<<<(EE / 4 + TB - 1) / TB, TB>>>((const int4*)src, (const int4*)dst);

    cudaStreamWaitEvent(0, evB, 0);

    k_gcn_node<<<gNode, TB>>>(b_gcn);

    k_gemm<64, 1><<<gGemm, TB>>>(nullptr, W1, as1, ad1, 1);
    k_gat_node<1><<<gNode, TB>>>(b1);

    k_gemm<64, 1><<<gGemm, TB>>>(nullptr, W2, as2, ad2, 1);
    k_gat_node<2><<<gNode, TB>>>(b2);

    k_pool<<<(NN + 63) / 64, TB>>>(batch);
    k_fc<<<GG, 64>>>(Wf1, bf1, Wf2, bf2, out);

    cudaStreamDestroy(s2);
    cudaEventDestroy(evA);
    cudaEventDestroy(evB);
}

// round 11
// speedup vs baseline: 1.0401x; 1.0401x over previous
#include <cuda_runtime.h>
#include <cuda_fp16.h>

#define NN 100000
#define EE 1600000
#define GG 2048
#define HD 64
#define SCAN_B 1024
#define SCAN_G ((NN + SCAN_B - 1) / SCAN_B)   // 98

// ---------------- scratch ----------------
__device__ float    g_hA[NN * HD];
__device__ __half   g_hw[NN * HD];
__device__ float    g_dinv[NN];
__device__ float    g_as[NN], g_ad[NN];
__device__ int      g_cnt[NN];          // stays zeroed between runs
__device__ int      g_rs[NN + 1];
__device__ int      g_cur[NN];
__device__ int      g_bsum[SCAN_G], g_boff[SCAN_G];
__device__ int      g_tick;             // stays zeroed between runs
__device__ uint2    c_pack[EE];         // (src, half2(es1,es2)) CSR-ordered
__device__ unsigned g_pool[GG * HD];    // re-armed by k_fc each run
__device__ float    g_v[32];

__device__ __forceinline__ unsigned encf(float f) {
    unsigned u = __float_as_uint(f);
    return (u & 0x80000000u) ? ~u : (u | 0x80000000u);
}
__device__ __forceinline__ float decf(unsigned u) {
    return __uint_as_float((u & 0x80000000u) ? (u & 0x7fffffffu) : ~u);
}
#define ENC_NEGINF 0x007fffffu

__device__ __forceinline__ float lrelu(float a) { return (a > 0.f) ? a : 0.2f * a; }

// ---------------- setup (R7-exact) ----------------

__global__ void k_cnt(const int4* __restrict__ dst4,
                      const float* __restrict__ We1, const float* __restrict__ ae1,
                      const float* __restrict__ We2, const float* __restrict__ ae2) {
    int i = blockIdx.x * blockDim.x + threadIdx.x;
    if (blockIdx.x == 0 && threadIdx.x < 32) {
        int t = threadIdx.x;
        const float* We = (t < 16) ? We1 : We2;
        const float* ae = (t < 16) ? ae1 : ae2;
        int j = t & 15;
        float s = 0.f;
        #pragma unroll 8
        for (int c = 0; c < HD; c++) s += We[j * HD + c] * ae[c];
        g_v[t] = s;
    }
    if (i < EE / 4) {
        int4 d = dst4[i];
        atomicAdd(&g_cnt[d.x], 1);
        atomicAdd(&g_cnt[d.y], 1);
        atomicAdd(&g_cnt[d.z], 1);
        atomicAdd(&g_cnt[d.w], 1);
    }
}

__global__ void k_scan1() {
    __shared__ int sh[SCAN_B];
    __shared__ int is_last;
    int t = threadIdx.x;
    int i = blockIdx.x * SCAN_B + t;
    int v = (i < NN) ? g_cnt[i] : 0;
    sh[t] = v;
    __syncthreads();
    for (int off = 1; off < SCAN_B; off <<= 1) {
        int x = (t >= off) ? sh[t - off] : 0;
        __syncthreads();
        sh[t] += x;
        __syncthreads();
    }
    if (i < NN) g_rs[i] = sh[t] - v;
    if (t == SCAN_B - 1) g_bsum[blockIdx.x] = sh[t];
    __threadfence();
    __syncthreads();
    if (t == 0) is_last = (atomicAdd(&g_tick, 1) == SCAN_G - 1) ? 1 : 0;
    __syncthreads();
    if (is_last) __threadfence();
    if (is_last && t < 32) {
        int lane = t;
        int base = lane * 4;
        int v0 = (base + 0 < SCAN_G) ? g_bsum[base + 0] : 0;
        int v1 = (base + 1 < SCAN_G) ? g_bsum[base + 1] : 0;
        int v2 = (base + 2 < SCAN_G) ? g_bsum[base + 2] : 0;
        int v3 = (base + 3 < SCAN_G) ? g_bsum[base + 3] : 0;
        int e1 = v0, e2 = v0 + v1, e3 = v0 + v1 + v2;
        int tot = e3 + v3;
        int x = tot;
        #pragma unroll
        for (int off = 1; off < 32; off <<= 1) {
            int y = __shfl_up_sync(0xffffffffu, x, off);
            if (lane >= off) x += y;
        }
        int excl = x - tot;
        if (base + 0 < SCAN_G) g_boff[base + 0] = excl;
        if (base + 1 < SCAN_G) g_boff[base + 1] = excl + e1;
        if (base + 2 < SCAN_G) g_boff[base + 2] = excl + e2;
        if (base + 3 < SCAN_G) g_boff[base + 3] = excl + e3;
        if (lane == 0) g_tick = 0;
    }
}

__global__ void k_scan3() {
    int i = blockIdx.x * SCAN_B + threadIdx.x;
    if (i < NN) {
        int cv = g_cnt[i];
        g_cnt[i] = 0;
        int rs = g_rs[i] + g_boff[blockIdx.x];
        g_rs[i] = rs;
        g_cur[i] = rs;
        g_dinv[i] = rsqrtf((float)(cv + 1));
    }
    if (i == 0) g_rs[NN] = EE;
}

__global__ void k_scatter(const float* __restrict__ ea,
                          const int* __restrict__ src, const int* __restrict__ dst) {
    int i = blockIdx.x * blockDim.x + threadIdx.x;
    if (i >= EE / 2) return;
    int i2 = i + EE / 2;
    const float4* pA = (const float4*)(ea + (size_t)i  * 16);
    const float4* pB = (const float4*)(ea + (size_t)i2 * 16);
    float4 qa0 = pA[0], qa1 = pA[1], qa2 = pA[2], qa3 = pA[3];
    float4 qb0 = pB[0], qb1 = pB[1], qb2 = pB[2], qb3 = pB[3];
    int dA = dst[i], dB = dst[i2];
    int sA = src[i], sB = src[i2];
    float ea_[16], eb_[16];
    ea_[0]=qa0.x; ea_[1]=qa0.y; ea_[2]=qa0.z; ea_[3]=qa0.w;
    ea_[4]=qa1.x; ea_[5]=qa1.y; ea_[6]=qa1.z; ea_[7]=qa1.w;
    ea_[8]=qa2.x; ea_[9]=qa2.y; ea_[10]=qa2.z; ea_[11]=qa2.w;
    ea_[12]=qa3.x; ea_[13]=qa3.y; ea_[14]=qa3.z; ea_[15]=qa3.w;
    eb_[0]=qb0.x; eb_[1]=qb0.y; eb_[2]=qb0.z; eb_[3]=qb0.w;
    eb_[4]=qb1.x; eb_[5]=qb1.y; eb_[6]=qb1.z; eb_[7]=qb1.w;
    eb_[8]=qb2.x; eb_[9]=qb2.y; eb_[10]=qb2.z; eb_[11]=qb2.w;
    eb_[12]=qb3.x; eb_[13]=qb3.y; eb_[14]=qb3.z; eb_[15]=qb3.w;
    float sA1 = 0.f, sA2 = 0.f, sB1 = 0.f, sB2 = 0.f;
    #pragma unroll
    for (int k = 0; k < 16; k++) {
        float v1 = g_v[k], v2 = g_v[16 + k];
        sA1 += ea_[k] * v1; sA2 += ea_[k] * v2;
        sB1 += eb_[k] * v1; sB2 += eb_[k] * v2;
    }
    int posA = atomicAdd(&g_cur[dA], 1);
    int posB = atomicAdd(&g_cur[dB], 1);
    __half2 hA = __floats2half2_rn(sA1, sA2);
    __half2 hB = __floats2half2_rn(sB1, sB2);
    uint2 pkA, pkB;
    pkA.x = (unsigned)sA; pkA.y = *reinterpret_cast<unsigned*>(&hA);
    pkB.x = (unsigned)sB; pkB.y = *reinterpret_cast<unsigned*>(&hB);
    c_pack[posA] = pkA;
    c_pack[posB] = pkB;
}

// ---------------- tensor-core GEMM (R7-exact) ----------------
template <int KD, int ATT>
__global__ void k_gemm(const float* __restrict__ Xext, const float* __restrict__ W,
                       const float* __restrict__ att_s, const float* __restrict__ att_d,
                       int useInternal) {
    const float* X = useInternal ? g_hA : Xext;
    __shared__ __half Xs[64][KD + 8];
    __shared__ __half Ws[KD][72];
    __shared__ float sred[64], dred[64];
    int tid = threadIdx.x;
    int node0 = blockIdx.x * 64;

    for (int i = tid; i < 64 * KD; i += 256) {
        int r = i / KD, k = i % KD;
        float v = (node0 + r < NN) ? X[(size_t)(node0 + r) * KD + k] : 0.f;
        Xs[r][k] = __float2half(v);
    }
    for (int i = tid; i < KD * 64; i += 256) {
        int k = i >> 6, n = i & 63;
        Ws[k][n] = __float2half(W[k * 64 + n]);
    }
    if (ATT && tid < 64) { sred[tid] = 0.f; dred[tid] = 0.f; }
    __syncthreads();

    int wid  = tid >> 5;
    int lane = tid & 31;
    int rt = wid >> 1;
    int ch = wid & 1;
    int g  = lane >> 2;
    int t2 = (lane & 3) * 2;
    int row0 = rt * 16;

    float c[4][4];
    #pragma unroll
    for (int nt = 0; nt < 4; nt++)
        #pragma unroll
        for (int q = 0; q < 4; q++) c[nt][q] = 0.f;

    #pragma unroll
    for (int ks = 0; ks < KD / 16; ks++) {
        int k0 = ks * 16;
        unsigned a0 = *(const unsigned*)&Xs[row0 + g    ][k0 + t2];
        unsigned a1 = *(const unsigned*)&Xs[row0 + g + 8][k0 + t2];
        unsigned a2 = *(const unsigned*)&Xs[row0 + g    ][k0 + t2 + 8];
        unsigned a3 = *(const unsigned*)&Xs[row0 + g + 8][k0 + t2 + 8];
        #pragma unroll
        for (int nt = 0; nt < 4; nt++) {
            int n0 = ch * 32 + nt * 8 + g;
            __half2 b0h = __halves2half2(Ws[k0 + t2    ][n0], Ws[k0 + t2 + 1][n0]);
            __half2 b1h = __halves2half2(Ws[k0 + t2 + 8][n0], Ws[k0 + t2 + 9][n0]);
            unsigned b0 = *reinterpret_cast<unsigned*>(&b0h);
            unsigned b1 = *reinterpret_cast<unsigned*>(&b1h);
            asm volatile(
                "mma.sync.aligned.m16n8k16.row.col.f32.f16.f16.f32 "
                "{%0,%1,%2,%3}, {%4,%5,%6,%7}, {%8,%9}, {%0,%1,%2,%3};"
                : "+f"(c[nt][0]), "+f"(c[nt][1]), "+f"(c[nt][2]), "+f"(c[nt][3])
                : "r"(a0), "r"(a1), "r"(a2), "r"(a3), "r"(b0), "r"(b1));
        }
    }

    int rowA = node0 + row0 + g;
    int rowB = rowA + 8;
    #pragma unroll
    for (int nt = 0; nt < 4; nt++) {
        int col = ch * 32 + nt * 8 + t2;
        if (rowA < NN)
            *(__half2*)&g_hw[(size_t)rowA * 64 + col] = __floats2half2_rn(c[nt][0], c[nt][1]);
        if (rowB < NN)
            *(__half2*)&g_hw[(size_t)rowB * 64 + col] = __floats2half2_rn(c[nt][2], c[nt][3]);
    }

    if (ATT) {
        float pAs = 0.f, pAd = 0.f, pBs = 0.f, pBd = 0.f;
        #pragma unroll
        for (int nt = 0; nt < 4; nt++) {
            int col = ch * 32 + nt * 8 + t2;
            float s0 = att_s[col], s1v = att_s[col + 1];
            float d0 = att_d[col], d1v = att_d[col + 1];
            pAs += c[nt][0] * s0 + c[nt][1] * s1v;
            pAd += c[nt][0] * d0 + c[nt][1] * d1v;
            pBs += c[nt][2] * s0 + c[nt][3] * s1v;
            pBd += c[nt][2] * d0 + c[nt][3] * d1v;
        }
        #pragma unroll
        for (int o = 1; o < 4; o <<= 1) {
            pAs += __shfl_xor_sync(0xffffffffu, pAs, o);
            pAd += __shfl_xor_sync(0xffffffffu, pAd, o);
            pBs += __shfl_xor_sync(0xffffffffu, pBs, o);
            pBd += __shfl_xor_sync(0xffffffffu, pBd, o);
        }
        if ((lane & 3) == 0) {
            atomicAdd(&sred[row0 + g],     pAs);
            atomicAdd(&dred[row0 + g],     pAd);
            atomicAdd(&sred[row0 + g + 8], pBs);
            atomicAdd(&dred[row0 + g + 8], pBd);
        }
        __syncthreads();
        if (tid < 64 && node0 + tid < NN) {
            g_as[node0 + tid] = sred[tid];
            g_ad[node0 + tid] = dred[tid];
        }
    }
}

// ---------------- gathers: 2 nodes per warp (16 lanes each) ----------------
// lane loads uint2 (4 half cols) of its half's row; one warp LDG covers 2 rows.

__device__ __forceinline__ void row4(int s, int hl, float* f) {
    uint2 r = *(const uint2*)((const char*)g_hw + ((size_t)s << 7) + (hl << 3));
    float2 f0 = __half22float2(*reinterpret_cast<__half2*>(&r.x));
    float2 f1 = __half22float2(*reinterpret_cast<__half2*>(&r.y));
    f[0] = f0.x; f[1] = f0.y; f[2] = f1.x; f[3] = f1.y;
}

__global__ void k_gcn_node(const float* __restrict__ b) {
    int lane = threadIdx.x & 31;
    int half = lane >> 4, hl = lane & 15;
    int node = (blockIdx.x * 8 + (threadIdx.x >> 5)) * 2 + half;   // NN even: always valid
    int rs = g_rs[node], re = g_rs[node + 1];
    int deg = re - rs;
    int trips = (deg + 15) >> 4;
    int wtrips = max(trips, __shfl_xor_sync(0xffffffffu, trips, 16));
    int sbase = half << 4;
    float acc0 = 0.f, acc1 = 0.f, acc2 = 0.f, acc3 = 0.f;
    for (int t = 0; t < wtrips; t++) {
        int jb = t << 4;
        int n = deg - jb; if (n > 16) n = 16;
        int s_l = 0; float w_l = 0.f;
        if (hl < n) {
            s_l = (int)c_pack[rs + jb + hl].x;
            w_l = g_dinv[s_l];
        }
        #pragma unroll 8
        for (int j = 0; j < 16; j++) {
            int s   = __shfl_sync(0xffffffffu, s_l, sbase + j);
            float w = __shfl_sync(0xffffffffu, w_l, sbase + j);
            if (j < n) {
                float f[4];
                row4(s, hl, f);
                acc0 += w * f[0]; acc1 += w * f[1];
                acc2 += w * f[2]; acc3 += w * f[3];
            }
        }
    }
    float di = g_dinv[node];
    float f[4];
    row4(node, hl, f);
    acc0 += di * f[0]; acc1 += di * f[1]; acc2 += di * f[2]; acc3 += di * f[3];
    float4 bb = ((const float4*)b)[hl];
    float4 o;
    o.x = fmaxf(acc0 * di + bb.x, 0.f);
    o.y = fmaxf(acc1 * di + bb.y, 0.f);
    o.z = fmaxf(acc2 * di + bb.z, 0.f);
    o.w = fmaxf(acc3 * di + bb.w, 0.f);
    ((float4*)(g_hA + (size_t)node * 64))[hl] = o;
}

template <int LAYER>
__global__ void k_gat_node(const float* __restrict__ b) {
    int lane = threadIdx.x & 31;
    int half = lane >> 4, hl = lane & 15;
    int node = (blockIdx.x * 8 + (threadIdx.x >> 5)) * 2 + half;
    int rs = g_rs[node], re = g_rs[node + 1];
    int deg = re - rs;
    int trips = (deg + 15) >> 4;
    int wtrips = max(trips, __shfl_xor_sync(0xffffffffu, trips, 16));
    int sbase = half << 4;
    float ad_n = g_ad[node];
    float acc0 = 0.f, acc1 = 0.f, acc2 = 0.f, acc3 = 0.f;
    float den_l = 0.f, es_l = 0.f;
    for (int t = 0; t < wtrips; t++) {
        int jb = t << 4;
        int n = deg - jb; if (n > 16) n = 16;
        int s_l = 0; float x_l = 0.f;
        if (hl < n) {
            uint2 q = c_pack[rs + jb + hl];
            s_l = (int)q.x;
            __half2 eh = *reinterpret_cast<__half2*>(&q.y);
            float e = (LAYER == 1) ? __low2float(eh) : __high2float(eh);
            x_l = __expf(lrelu(g_as[s_l] + ad_n + e));
            den_l += x_l;
            es_l  += e;
        }
        #pragma unroll 8
        for (int j = 0; j < 16; j++) {
            int s   = __shfl_sync(0xffffffffu, s_l, sbase + j);
            float x = __shfl_sync(0xffffffffu, x_l, sbase + j);
            if (j < n) {
                float f[4];
                row4(s, hl, f);
                acc0 += x * f[0]; acc1 += x * f[1];
                acc2 += x * f[2]; acc3 += x * f[3];
            }
        }
    }
    // reduce den/es within the 16-lane half
    #pragma unroll
    for (int o = 8; o; o >>= 1) {
        den_l += __shfl_xor_sync(0xffffffffu, den_l, o);
        es_l  += __shfl_xor_sync(0xffffffffu, es_l, o);
    }
    float cnt = (float)deg;
    float xs = __expf(lrelu(g_as[node] + ad_n + es_l / fmaxf(cnt, 1.f)));
    float den = den_l + xs;
    float f[4];
    row4(node, hl, f);
    acc0 += xs * f[0]; acc1 += xs * f[1]; acc2 += xs * f[2]; acc3 += xs * f[3];
    float inv = 1.f / den;
    float4 bb = ((const float4*)b)[hl];
    float4 o;
    o.x = fmaxf(acc0 * inv + bb.x, 0.f);
    o.y = fmaxf(acc1 * inv + bb.y, 0.f);
    o.z = fmaxf(acc2 * inv + bb.z, 0.f);
    o.w = fmaxf(acc3 * inv + bb.w, 0.f);
    ((float4*)(g_hA + (size_t)node * 64))[hl] = o;
}

// ---------------- pool + head (R7-exact) ----------------

__global__ void k_pool(const int* __restrict__ batch) {
    int c   = threadIdx.x & 63;
    int grp = threadIdx.x >> 6;
    int n0  = blockIdx.x * 64 + grp * 16;
    if (n0 >= NN) return;
    int curg = batch[n0];
    float m = -3.402823466e+38f;
    for (int k = 0; k < 16; k++) {
        int n = n0 + k;
        if (n >= NN) break;
        int bg = batch[n];
        if (bg != curg) {
            atomicMax(&g_pool[curg * 64 + c], encf(m));
            m = -3.402823466e+38f;
            curg = bg;
        }
        m = fmaxf(m, g_hA[(size_t)n * 64 + c]);
    }
    atomicMax(&g_pool[curg * 64 + c], encf(m));
}

__global__ void k_fc(const float* __restrict__ W1, const float* __restrict__ b1,
                     const float* __restrict__ W2, const float* __restrict__ b2,
                     float* __restrict__ out) {
    __shared__ float t0[64], t1[64];
    int g = blockIdx.x, c = threadIdx.x;
    t0[c] = decf(g_pool[g * 64 + c]);
    g_pool[g * 64 + c] = ENC_NEGINF;
    __syncthreads();
    float s = 0.f;
    #pragma unroll 8
    for (int k = 0; k < 64; k++) s += t0[k] * W1[k * 64 + c];
    t1[c] = fmaxf(s + b1[c], 0.f);
    __syncthreads();
    float o = 0.f;
    #pragma unroll 8
    for (int k = 0; k < 64; k++) o += t1[k] * W2[k * 64 + c];
    out[g * 64 + c] = o + b2[c];
}

// ---------------- launch (R7-exact) ----------------
extern "C" void kernel_launch(void* const* d_in, const int* in_sizes, int n_in,
                              void* d_out, int out_size) {
    const float* x     = (const float*)d_in[0];
    const int*   ei    = (const int*)  d_in[1];
    const float* ea    = (const float*)d_in[2];
    const int*   batch = (const int*)  d_in[3];
    const float* W_gcn = (const float*)d_in[4];
    const float* b_gcn = (const float*)d_in[5];
    const float* W1    = (const float*)d_in[6];
    const float* We1   = (const float*)d_in[7];
    const float* as1   = (const float*)d_in[8];
    const float* ad1   = (const float*)d_in[9];
    const float* ae1   = (const float*)d_in[10];
    const float* b1    = (const float*)d_in[11];
    const float* W2    = (const float*)d_in[12];
    const float* We2   = (const float*)d_in[13];
    const float* as2   = (const float*)d_in[14];
    const float* ad2   = (const float*)d_in[15];
    const float* ae2   = (const float*)d_in[16];
    const float* b2    = (const float*)d_in[17];
    const float* Wf1   = (const float*)d_in[18];
    const float* bf1   = (const float*)d_in[19];
    const float* Wf2   = (const float*)d_in[20];
    const float* bf2   = (const float*)d_in[21];
    float* out = (float*)d_out;

    const int* src = ei;
    const int* dst = ei + EE;

    const int TB = 256;
    const int gGemm = (NN + 63) / 64;
    const int gNode = NN / 16;          // 2 nodes/warp * 8 warps/block

    cudaStream_t s2;
    cudaEvent_t evA, evB;
    cudaStreamCreateWithFlags(&s2, cudaStreamNonBlocking);
    cudaEventCreateWithFlags(&evA, cudaEventDisableTiming);
    cudaEventCreateWithFlags(&evB, cudaEventDisableTiming);

    cudaEventRecord(evA, 0);
    cudaStreamWaitEvent(s2, evA, 0);
    k_gemm<128, 0><<<gGemm, TB, 0, s2>>>(x, W_gcn, nullptr, nullptr, 0);
    cudaEventRecord(evB, s2);

    k_cnt<<<(EE / 4 + TB - 1) / TB, TB>>>((const int4*)dst, We1, ae1, We2, ae2);
    k_scan1<<<SCAN_G, SCAN_B>>>();
    k_scan3<<<SCAN_G, SCAN_B>>>();
    k_scatter<<<(EE / 2 + TB - 1) / TB, TB>>>(ea, src, dst);

    cudaStreamWaitEvent(0, evB, 0);

    k_gcn_node<<<gNode, TB>>>(b_gcn);

    k_gemm<64, 1><<<gGemm, TB>>>(nullptr, W1, as1, ad1, 1);
    k_gat_node<1><<<gNode, TB>>>(b1);

    k_gemm<64, 1><<<gGemm, TB>>>(nullptr, W2, as2, ad2, 1);
    k_gat_node<2><<<gNode, TB>>>(b2);

    k_pool<<<(NN + 63) / 64, TB>>>(batch);
    k_fc<<<GG, 64>>>(Wf1, bf1, Wf2, bf2, out);

    cudaStreamDestroy(s2);
    cudaEventDestroy(evA);
    cudaEventDestroy(evB);
}

// round 12
// speedup vs baseline: 1.0758x; 1.0344x over previous
#include <cuda_runtime.h>
#include <cuda_fp16.h>

#define NN 100000
#define EE 1600000
#define GG 2048
#define HD 64
#define SCAN_B 1024
#define SCAN_G ((NN + SCAN_B - 1) / SCAN_B)   // 98

// ---------------- scratch ----------------
__device__ float    g_hA[NN * HD];
__device__ __half   g_hw[NN * HD];
__device__ float    g_dinv[NN];
__device__ float    g_as[NN], g_ad[NN];
__device__ int      g_cnt[NN];          // stays zeroed between runs
__device__ int      g_rs[NN + 1];
__device__ int      g_cur[NN];
__device__ int      g_bsum[SCAN_G], g_boff[SCAN_G];
__device__ int      g_tick;             // stays zeroed between runs
__device__ uint2    c_pack[EE];         // (src, half2(es1,es2)) CSR-ordered
__device__ unsigned g_pool[GG * HD];    // re-armed by k_fc each run
__device__ float    g_v[32];

__device__ __forceinline__ unsigned encf(float f) {
    unsigned u = __float_as_uint(f);
    return (u & 0x80000000u) ? ~u : (u | 0x80000000u);
}
__device__ __forceinline__ float decf(unsigned u) {
    return __uint_as_float((u & 0x80000000u) ? (u & 0x7fffffffu) : ~u);
}
#define ENC_NEGINF 0x007fffffu

__device__ __forceinline__ float lrelu(float a) { return (a > 0.f) ? a : 0.2f * a; }

// ---------------- setup ----------------

__global__ void k_cnt(const int4* __restrict__ dst4,
                      const float* __restrict__ We1, const float* __restrict__ ae1,
                      const float* __restrict__ We2, const float* __restrict__ ae2) {
    int i = blockIdx.x * blockDim.x + threadIdx.x;
    if (blockIdx.x == 0 && threadIdx.x < 32) {
        int t = threadIdx.x;
        const float* We = (t < 16) ? We1 : We2;
        const float* ae = (t < 16) ? ae1 : ae2;
        int j = t & 15;
        float s = 0.f;
        #pragma unroll 8
        for (int c = 0; c < HD; c++) s += We[j * HD + c] * ae[c];
        g_v[t] = s;
    }
    if (i < EE / 4) {
        int4 d = dst4[i];
        atomicAdd(&g_cnt[d.x], 1);
        atomicAdd(&g_cnt[d.y], 1);
        atomicAdd(&g_cnt[d.z], 1);
        atomicAdd(&g_cnt[d.w], 1);
    }
}

// warp-shuffle block scan: 2 barriers instead of 20
__global__ void k_scan1() {
    __shared__ int wsum[32];
    __shared__ int is_last;
    int t = threadIdx.x;
    int i = blockIdx.x * SCAN_B + t;
    int v = (i < NN) ? g_cnt[i] : 0;
    int lane = t & 31, w = t >> 5;
    // warp inclusive scan
    int x = v;
    #pragma unroll
    for (int off = 1; off < 32; off <<= 1) {
        int y = __shfl_up_sync(0xffffffffu, x, off);
        if (lane >= off) x += y;
    }
    if (lane == 31) wsum[w] = x;
    __syncthreads();
    if (w == 0) {
        int s = wsum[lane];
        #pragma unroll
        for (int off = 1; off < 32; off <<= 1) {
            int y = __shfl_up_sync(0xffffffffu, s, off);
            if (lane >= off) s += y;
        }
        wsum[lane] = s;
    }
    __syncthreads();
    int incl = x + ((w > 0) ? wsum[w - 1] : 0);
    if (i < NN) g_rs[i] = incl - v;
    if (t == SCAN_B - 1) g_bsum[blockIdx.x] = incl;
    __threadfence();
    __syncthreads();
    if (t == 0) is_last = (atomicAdd(&g_tick, 1) == SCAN_G - 1) ? 1 : 0;
    __syncthreads();
    if (is_last) __threadfence();
    if (is_last && t < 32) {
        int base = lane * 4;
        int v0 = (base + 0 < SCAN_G) ? g_bsum[base + 0] : 0;
        int v1 = (base + 1 < SCAN_G) ? g_bsum[base + 1] : 0;
        int v2 = (base + 2 < SCAN_G) ? g_bsum[base + 2] : 0;
        int v3 = (base + 3 < SCAN_G) ? g_bsum[base + 3] : 0;
        int e1 = v0, e2 = v0 + v1, e3 = v0 + v1 + v2;
        int tot = e3 + v3;
        int xx = tot;
        #pragma unroll
        for (int off = 1; off < 32; off <<= 1) {
            int y = __shfl_up_sync(0xffffffffu, xx, off);
            if (lane >= off) xx += y;
        }
        int excl = xx - tot;
        if (base + 0 < SCAN_G) g_boff[base + 0] = excl;
        if (base + 1 < SCAN_G) g_boff[base + 1] = excl + e1;
        if (base + 2 < SCAN_G) g_boff[base + 2] = excl + e2;
        if (base + 3 < SCAN_G) g_boff[base + 3] = excl + e3;
        if (lane == 0) g_tick = 0;
    }
}

__global__ void k_scan3() {
    int i = blockIdx.x * SCAN_B + threadIdx.x;
    if (i < NN) {
        int cv = g_cnt[i];
        g_cnt[i] = 0;
        int rs = g_rs[i] + g_boff[blockIdx.x];
        g_rs[i] = rs;
        g_cur[i] = rs;
        g_dinv[i] = rsqrtf((float)(cv + 1));
    }
    if (i == 0) g_rs[NN] = EE;
}

__global__ void k_scatter(const float* __restrict__ ea,
                          const int* __restrict__ src, const int* __restrict__ dst) {
    int i = blockIdx.x * blockDim.x + threadIdx.x;
    if (i >= EE / 2) return;
    int i2 = i + EE / 2;
    const float4* pA = (const float4*)(ea + (size_t)i  * 16);
    const float4* pB = (const float4*)(ea + (size_t)i2 * 16);
    float4 qa0 = pA[0], qa1 = pA[1], qa2 = pA[2], qa3 = pA[3];
    float4 qb0 = pB[0], qb1 = pB[1], qb2 = pB[2], qb3 = pB[3];
    int dA = dst[i], dB = dst[i2];
    int sA = src[i], sB = src[i2];
    float ea_[16], eb_[16];
    ea_[0]=qa0.x; ea_[1]=qa0.y; ea_[2]=qa0.z; ea_[3]=qa0.w;
    ea_[4]=qa1.x; ea_[5]=qa1.y; ea_[6]=qa1.z; ea_[7]=qa1.w;
    ea_[8]=qa2.x; ea_[9]=qa2.y; ea_[10]=qa2.z; ea_[11]=qa2.w;
    ea_[12]=qa3.x; ea_[13]=qa3.y; ea_[14]=qa3.z; ea_[15]=qa3.w;
    eb_[0]=qb0.x; eb_[1]=qb0.y; eb_[2]=qb0.z; eb_[3]=qb0.w;
    eb_[4]=qb1.x; eb_[5]=qb1.y; eb_[6]=qb1.z; eb_[7]=qb1.w;
    eb_[8]=qb2.x; eb_[9]=qb2.y; eb_[10]=qb2.z; eb_[11]=qb2.w;
    eb_[12]=qb3.x; eb_[13]=qb3.y; eb_[14]=qb3.z; eb_[15]=qb3.w;
    float sA1 = 0.f, sA2 = 0.f, sB1 = 0.f, sB2 = 0.f;
    #pragma unroll
    for (int k = 0; k < 16; k++) {
        float v1 = g_v[k], v2 = g_v[16 + k];
        sA1 += ea_[k] * v1; sA2 += ea_[k] * v2;
        sB1 += eb_[k] * v1; sB2 += eb_[k] * v2;
    }
    int posA = atomicAdd(&g_cur[dA], 1);
    int posB = atomicAdd(&g_cur[dB], 1);
    __half2 hA = __floats2half2_rn(sA1, sA2);
    __half2 hB = __floats2half2_rn(sB1, sB2);
    uint2 pkA, pkB;
    pkA.x = (unsigned)sA; pkA.y = *reinterpret_cast<unsigned*>(&hA);
    pkB.x = (unsigned)sB; pkB.y = *reinterpret_cast<unsigned*>(&hB);
    c_pack[posA] = pkA;
    c_pack[posB] = pkB;
}

// ---------------- tensor-core GEMM (R7-exact) ----------------
template <int KD, int ATT>
__global__ void k_gemm(const float* __restrict__ Xext, const float* __restrict__ W,
                       const float* __restrict__ att_s, const float* __restrict__ att_d,
                       int useInternal) {
    const float* X = useInternal ? g_hA : Xext;
    __shared__ __half Xs[64][KD + 8];
    __shared__ __half Ws[KD][72];
    __shared__ float sred[64], dred[64];
    int tid = threadIdx.x;
    int node0 = blockIdx.x * 64;

    for (int i = tid; i < 64 * KD; i += 256) {
        int r = i / KD, k = i % KD;
        float v = (node0 + r < NN) ? X[(size_t)(node0 + r) * KD + k] : 0.f;
        Xs[r][k] = __float2half(v);
    }
    for (int i = tid; i < KD * 64; i += 256) {
        int k = i >> 6, n = i & 63;
        Ws[k][n] = __float2half(W[k * 64 + n]);
    }
    if (ATT && tid < 64) { sred[tid] = 0.f; dred[tid] = 0.f; }
    __syncthreads();

    int wid  = tid >> 5;
    int lane = tid & 31;
    int rt = wid >> 1;
    int ch = wid & 1;
    int g  = lane >> 2;
    int t2 = (lane & 3) * 2;
    int row0 = rt * 16;

    float c[4][4];
    #pragma unroll
    for (int nt = 0; nt < 4; nt++)
        #pragma unroll
        for (int q = 0; q < 4; q++) c[nt][q] = 0.f;

    #pragma unroll
    for (int ks = 0; ks < KD / 16; ks++) {
        int k0 = ks * 16;
        unsigned a0 = *(const unsigned*)&Xs[row0 + g    ][k0 + t2];
        unsigned a1 = *(const unsigned*)&Xs[row0 + g + 8][k0 + t2];
        unsigned a2 = *(const unsigned*)&Xs[row0 + g    ][k0 + t2 + 8];
        unsigned a3 = *(const unsigned*)&Xs[row0 + g + 8][k0 + t2 + 8];
        #pragma unroll
        for (int nt = 0; nt < 4; nt++) {
            int n0 = ch * 32 + nt * 8 + g;
            __half2 b0h = __halves2half2(Ws[k0 + t2    ][n0], Ws[k0 + t2 + 1][n0]);
            __half2 b1h = __halves2half2(Ws[k0 + t2 + 8][n0], Ws[k0 + t2 + 9][n0]);
            unsigned b0 = *reinterpret_cast<unsigned*>(&b0h);
            unsigned b1 = *reinterpret_cast<unsigned*>(&b1h);
            asm volatile(
                "mma.sync.aligned.m16n8k16.row.col.f32.f16.f16.f32 "
                "{%0,%1,%2,%3}, {%4,%5,%6,%7}, {%8,%9}, {%0,%1,%2,%3};"
                : "+f"(c[nt][0]), "+f"(c[nt][1]), "+f"(c[nt][2]), "+f"(c[nt][3])
                : "r"(a0), "r"(a1), "r"(a2), "r"(a3), "r"(b0), "r"(b1));
        }
    }

    int rowA = node0 + row0 + g;
    int rowB = rowA + 8;
    #pragma unroll
    for (int nt = 0; nt < 4; nt++) {
        int col = ch * 32 + nt * 8 + t2;
        if (rowA < NN)
            *(__half2*)&g_hw[(size_t)rowA * 64 + col] = __floats2half2_rn(c[nt][0], c[nt][1]);
        if (rowB < NN)
            *(__half2*)&g_hw[(size_t)rowB * 64 + col] = __floats2half2_rn(c[nt][2], c[nt][3]);
    }

    if (ATT) {
        float pAs = 0.f, pAd = 0.f, pBs = 0.f, pBd = 0.f;
        #pragma unroll
        for (int nt = 0; nt < 4; nt++) {
            int col = ch * 32 + nt * 8 + t2;
            float s0 = att_s[col], s1v = att_s[col + 1];
            float d0 = att_d[col], d1v = att_d[col + 1];
            pAs += c[nt][0] * s0 + c[nt][1] * s1v;
            pAd += c[nt][0] * d0 + c[nt][1] * d1v;
            pBs += c[nt][2] * s0 + c[nt][3] * s1v;
            pBd += c[nt][2] * d0 + c[nt][3] * d1v;
        }
        #pragma unroll
        for (int o = 1; o < 4; o <<= 1) {
            pAs += __shfl_xor_sync(0xffffffffu, pAs, o);
            pAd += __shfl_xor_sync(0xffffffffu, pAd, o);
            pBs += __shfl_xor_sync(0xffffffffu, pBs, o);
            pBd += __shfl_xor_sync(0xffffffffu, pBd, o);
        }
        if ((lane & 3) == 0) {
            atomicAdd(&sred[row0 + g],     pAs);
            atomicAdd(&dred[row0 + g],     pAd);
            atomicAdd(&sred[row0 + g + 8], pBs);
            atomicAdd(&dred[row0 + g + 8], pBd);
        }
        __syncthreads();
        if (tid < 64 && node0 + tid < NN) {
            g_as[node0 + tid] = sred[tid];
            g_ad[node0 + tid] = dred[tid];
        }
    }
}

// ---------------- gathers (R7-exact) ----------------

__device__ __forceinline__ float2 hwrow(int s, int lane) {
    __half2 v = *((const __half2*)(g_hw + (size_t)s * 64) + lane);
    return __half22float2(v);
}

__global__ void k_gcn_node(const float* __restrict__ b) {
    int node = blockIdx.x * 8 + (threadIdx.x >> 5);
    int lane = threadIdx.x & 31;
    if (node >= NN) return;
    int rs = g_rs[node], re = g_rs[node + 1];
    float a0 = 0.f, a1 = 0.f;
    for (int jb = rs; jb < re; jb += 32) {
        int n = re - jb; if (n > 32) n = 32;
        int s_l = 0; float w_l = 0.f;
        if (lane < n) {
            s_l = (int)c_pack[jb + lane].x;
            w_l = g_dinv[s_l];
        }
        #pragma unroll 8
        for (int j = 0; j < n; j++) {
            int s   = __shfl_sync(0xffffffffu, s_l, j);
            float w = __shfl_sync(0xffffffffu, w_l, j);
            float2 f = hwrow(s, lane);
            a0 += w * f.x; a1 += w * f.y;
        }
    }
    float di = g_dinv[node];
    float2 fs = hwrow(node, lane);
    a0 += di * fs.x; a1 += di * fs.y;
    float2 bb = ((const float2*)b)[lane];
    float2 o;
    o.x = fmaxf(a0 * di + bb.x, 0.f);
    o.y = fmaxf(a1 * di + bb.y, 0.f);
    ((float2*)(g_hA + (size_t)node * 64))[lane] = o;
}

template <int LAYER>
__global__ void k_gat_node(const float* __restrict__ b) {
    int node = blockIdx.x * 8 + (threadIdx.x >> 5);
    int lane = threadIdx.x & 31;
    if (node >= NN) return;
    int rs = g_rs[node], re = g_rs[node + 1];
    float ad_n = g_ad[node];
    float a0 = 0.f, a1 = 0.f, den_l = 0.f, es_l = 0.f;
    for (int jb = rs; jb < re; jb += 32) {
        int n = re - jb; if (n > 32) n = 32;
        int s_l = 0; float x_l = 0.f;
        if (lane < n) {
            uint2 q = c_pack[jb + lane];
            s_l = (int)q.x;
            __half2 eh = *reinterpret_cast<__half2*>(&q.y);
            float e = (LAYER == 1) ? __low2float(eh) : __high2float(eh);
            x_l = __expf(lrelu(g_as[s_l] + ad_n + e));
            den_l += x_l;
            es_l  += e;
        }
        #pragma unroll 8
        for (int j = 0; j < n; j++) {
            int s   = __shfl_sync(0xffffffffu, s_l, j);
            float x = __shfl_sync(0xffffffffu, x_l, j);
            float2 f = hwrow(s, lane);
            a0 += x * f.x; a1 += x * f.y;
        }
    }
    #pragma unroll
    for (int o = 16; o; o >>= 1) {
        den_l += __shfl_xor_sync(0xffffffffu, den_l, o);
        es_l  += __shfl_xor_sync(0xffffffffu, es_l, o);
    }
    float cnt = (float)(re - rs);
    float x = __expf(lrelu(g_as[node] + ad_n + es_l / fmaxf(cnt, 1.f)));
    float den = den_l + x;
    float2 fs = hwrow(node, lane);
    a0 += x * fs.x; a1 += x * fs.y;
    float inv = 1.f / den;
    float2 bb = ((const float2*)b)[lane];
    float2 o;
    o.x = fmaxf(a0 * inv + bb.x, 0.f);
    o.y = fmaxf(a1 * inv + bb.y, 0.f);
    ((float2*)(g_hA + (size_t)node * 64))[lane] = o;
}

// ---------------- pool + head (R7-exact) ----------------

__global__ void k_pool(const int* __restrict__ batch) {
    int c   = threadIdx.x & 63;
    int grp = threadIdx.x >> 6;
    int n0  = blockIdx.x * 64 + grp * 16;
    if (n0 >= NN) return;
    int curg = batch[n0];
    float m = -3.402823466e+38f;
    for (int k = 0; k < 16; k++) {
        int n = n0 + k;
        if (n >= NN) break;
        int bg = batch[n];
        if (bg != curg) {
            atomicMax(&g_pool[curg * 64 + c], encf(m));
            m = -3.402823466e+38f;
            curg = bg;
        }
        m = fmaxf(m, g_hA[(size_t)n * 64 + c]);
    }
    atomicMax(&g_pool[curg * 64 + c], encf(m));
}

__global__ void k_fc(const float* __restrict__ W1, const float* __restrict__ b1,
                     const float* __restrict__ W2, const float* __restrict__ b2,
                     float* __restrict__ out) {
    __shared__ float t0[64], t1[64];
    int g = blockIdx.x, c = threadIdx.x;
    t0[c] = decf(g_pool[g * 64 + c]);
    g_pool[g * 64 + c] = ENC_NEGINF;
    __syncthreads();
    float s = 0.f;
    #pragma unroll 8
    for (int k = 0; k < 64; k++) s += t0[k] * W1[k * 64 + c];
    t1[c] = fmaxf(s + b1[c], 0.f);
    __syncthreads();
    float o = 0.f;
    #pragma unroll 8
    for (int k = 0; k < 64; k++) o += t1[k] * W2[k * 64 + c];
    out[g * 64 + c] = o + b2[c];
}

// ---------------- launch (R7-exact) ----------------
extern "C" void kernel_launch(void* const* d_in, const int* in_sizes, int n_in,
                              void* d_out, int out_size) {
    const float* x     = (const float*)d_in[0];
    const int*   ei    = (const int*)  d_in[1];
    const float* ea    = (const float*)d_in[2];
    const int*   batch = (const int*)  d_in[3];
    const float* W_gcn = (const float*)d_in[4];
    const float* b_gcn = (const float*)d_in[5];
    const float* W1    = (const float*)d_in[6];
    const float* We1   = (const float*)d_in[7];
    const float* as1   = (const float*)d_in[8];
    const float* ad1   = (const float*)d_in[9];
    const float* ae1   = (const float*)d_in[10];
    const float* b1    = (const float*)d_in[11];
    const float* W2    = (const float*)d_in[12];
    const float* We2   = (const float*)d_in[13];
    const float* as2   = (const float*)d_in[14];
    const float* ad2   = (const float*)d_in[15];
    const float* ae2   = (const float*)d_in[16];
    const float* b2    = (const float*)d_in[17];
    const float* Wf1   = (const float*)d_in[18];
    const float* bf1   = (const float*)d_in[19];
    const float* Wf2   = (const float*)d_in[20];
    const float* bf2   = (const float*)d_in[21];
    float* out = (float*)d_out;

    const int* src = ei;
    const int* dst = ei + EE;

    const int TB = 256;
    const int gGemm = (NN + 63) / 64;
    const int gNode = (NN + 7) / 8;

    cudaStream_t s2;
    cudaEvent_t evA, evB;
    cudaStreamCreateWithFlags(&s2, cudaStreamNonBlocking);
    cudaEventCreateWithFlags(&evA, cudaEventDisableTiming);
    cudaEventCreateWithFlags(&evB, cudaEventDisableTiming);

    cudaEventRecord(evA, 0);
    cudaStreamWaitEvent(s2, evA, 0);
    k_gemm<128, 0><<<gGemm, TB, 0, s2>>>(x, W_gcn, nullptr, nullptr, 0);
    cudaEventRecord(evB, s2);

    k_cnt<<<(EE / 4 + TB - 1) / TB, TB>>>((const int4*)dst, We1, ae1, We2, ae2);
    k_scan1<<<SCAN_G, SCAN_B>>>();
    k_scan3<<<SCAN_G, SCAN_B>>>();
    k_scatter<<<(EE / 2 + TB - 1) / TB, TB>>>(ea, src, dst);

    cudaStreamWaitEvent(0, evB, 0);

    k_gcn_node<<<gNode, TB>>>(b_gcn);

    k_gemm<64, 1><<<gGemm, TB>>>(nullptr, W1, as1, ad1, 1);
    k_gat_node<1><<<gNode, TB>>>(b1);

    k_gemm<64, 1><<<gGemm, TB>>>(nullptr, W2, as2, ad2, 1);
    k_gat_node<2><<<gNode, TB>>>(b2);

    k_pool<<<(NN + 63) / 64, TB>>>(batch);
    k_fc<<<GG, 64>>>(Wf1, bf1, Wf2, bf2, out);

    cudaStreamDestroy(s2);
    cudaEventDestroy(evA);
    cudaEventDestroy(evB);
}

// round 13
// speedup vs baseline: 1.0934x; 1.0164x over previous
#include <cuda_runtime.h>
#include <cuda_fp16.h>

#define NN 100000
#define EE 1600000
#define GG 2048
#define HD 64
#define SCAN_B 1024
#define SCAN_G ((NN + SCAN_B - 1) / SCAN_B)   // 98

// ---------------- scratch ----------------
__device__ float    g_hA[NN * HD];      // fp32 final-layer activations (pool input)
__device__ __half   g_hB[NN * HD];      // fp16 inter-layer activations (GEMM input)
__device__ __half   g_hw[NN * HD];      // fp16 pre-aggregation features
__device__ float    g_dinv[NN];
__device__ float    g_as[NN], g_ad[NN];
__device__ int      g_cnt[NN];          // stays zeroed between runs
__device__ int      g_rs[NN + 1];
__device__ int      g_cur[NN];
__device__ int      g_bsum[SCAN_G], g_boff[SCAN_G];
__device__ int      g_tick;             // stays zeroed between runs
__device__ uint2    c_pack[EE];         // (src, half2(es1,es2)) CSR-ordered
__device__ unsigned g_pool[GG * HD];    // re-armed by k_fc each run
__device__ float    g_v[32];

__device__ __forceinline__ unsigned encf(float f) {
    unsigned u = __float_as_uint(f);
    return (u & 0x80000000u) ? ~u : (u | 0x80000000u);
}
__device__ __forceinline__ float decf(unsigned u) {
    return __uint_as_float((u & 0x80000000u) ? (u & 0x7fffffffu) : ~u);
}
#define ENC_NEGINF 0x007fffffu

__device__ __forceinline__ float lrelu(float a) { return (a > 0.f) ? a : 0.2f * a; }

// ---------------- setup ----------------

__global__ void k_cnt(const int4* __restrict__ dst4,
                      const float* __restrict__ We1, const float* __restrict__ ae1,
                      const float* __restrict__ We2, const float* __restrict__ ae2) {
    int i = blockIdx.x * blockDim.x + threadIdx.x;
    if (blockIdx.x == 0 && threadIdx.x < 32) {
        int t = threadIdx.x;
        const float* We = (t < 16) ? We1 : We2;
        const float* ae = (t < 16) ? ae1 : ae2;
        int j = t & 15;
        float s = 0.f;
        #pragma unroll 8
        for (int c = 0; c < HD; c++) s += We[j * HD + c] * ae[c];
        g_v[t] = s;
    }
    if (i < EE / 4) {
        int4 d = dst4[i];
        atomicAdd(&g_cnt[d.x], 1);
        atomicAdd(&g_cnt[d.y], 1);
        atomicAdd(&g_cnt[d.z], 1);
        atomicAdd(&g_cnt[d.w], 1);
    }
}

// warp-shuffle block scan (R12)
__global__ void k_scan1() {
    __shared__ int wsum[32];
    __shared__ int is_last;
    int t = threadIdx.x;
    int i = blockIdx.x * SCAN_B + t;
    int v = (i < NN) ? g_cnt[i] : 0;
    int lane = t & 31, w = t >> 5;
    int x = v;
    #pragma unroll
    for (int off = 1; off < 32; off <<= 1) {
        int y = __shfl_up_sync(0xffffffffu, x, off);
        if (lane >= off) x += y;
    }
    if (lane == 31) wsum[w] = x;
    __syncthreads();
    if (w == 0) {
        int s = wsum[lane];
        #pragma unroll
        for (int off = 1; off < 32; off <<= 1) {
            int y = __shfl_up_sync(0xffffffffu, s, off);
            if (lane >= off) s += y;
        }
        wsum[lane] = s;
    }
    __syncthreads();
    int incl = x + ((w > 0) ? wsum[w - 1] : 0);
    if (i < NN) g_rs[i] = incl - v;
    if (t == SCAN_B - 1) g_bsum[blockIdx.x] = incl;
    __threadfence();
    __syncthreads();
    if (t == 0) is_last = (atomicAdd(&g_tick, 1) == SCAN_G - 1) ? 1 : 0;
    __syncthreads();
    if (is_last) __threadfence();
    if (is_last && t < 32) {
        int base = lane * 4;
        int v0 = (base + 0 < SCAN_G) ? g_bsum[base + 0] : 0;
        int v1 = (base + 1 < SCAN_G) ? g_bsum[base + 1] : 0;
        int v2 = (base + 2 < SCAN_G) ? g_bsum[base + 2] : 0;
        int v3 = (base + 3 < SCAN_G) ? g_bsum[base + 3] : 0;
        int e1 = v0, e2 = v0 + v1, e3 = v0 + v1 + v2;
        int tot = e3 + v3;
        int xx = tot;
        #pragma unroll
        for (int off = 1; off < 32; off <<= 1) {
            int y = __shfl_up_sync(0xffffffffu, xx, off);
            if (lane >= off) xx += y;
        }
        int excl = xx - tot;
        if (base + 0 < SCAN_G) g_boff[base + 0] = excl;
        if (base + 1 < SCAN_G) g_boff[base + 1] = excl + e1;
        if (base + 2 < SCAN_G) g_boff[base + 2] = excl + e2;
        if (base + 3 < SCAN_G) g_boff[base + 3] = excl + e3;
        if (lane == 0) g_tick = 0;
    }
}

__global__ void k_scan3() {
    int i = blockIdx.x * SCAN_B + threadIdx.x;
    if (i < NN) {
        int cv = g_cnt[i];
        g_cnt[i] = 0;
        int rs = g_rs[i] + g_boff[blockIdx.x];
        g_rs[i] = rs;
        g_cur[i] = rs;
        g_dinv[i] = rsqrtf((float)(cv + 1));
    }
    if (i == 0) g_rs[NN] = EE;
}

// 4 edges/thread scatter (4 coalesced quarter-streams, incremental dots)
__global__ void k_scatter(const float* __restrict__ ea,
                          const int* __restrict__ src, const int* __restrict__ dst) {
    int i = blockIdx.x * blockDim.x + threadIdx.x;
    const int Q = EE / 4;
    if (i >= Q) return;
    float s1[4], s2[4];
    int sv[4], dv[4];
    #pragma unroll
    for (int e = 0; e < 4; e++) {
        int idx = i + e * Q;
        sv[e] = src[idx];
        dv[e] = dst[idx];
        const float4* p = (const float4*)(ea + (size_t)idx * 16);
        float a1 = 0.f, a2 = 0.f;
        #pragma unroll
        for (int k = 0; k < 4; k++) {
            float4 q = p[k];
            a1 += q.x * g_v[4*k] + q.y * g_v[4*k+1] + q.z * g_v[4*k+2] + q.w * g_v[4*k+3];
            a2 += q.x * g_v[16+4*k] + q.y * g_v[16+4*k+1] + q.z * g_v[16+4*k+2] + q.w * g_v[16+4*k+3];
        }
        s1[e] = a1; s2[e] = a2;
    }
    #pragma unroll
    for (int e = 0; e < 4; e++) {
        int pos = atomicAdd(&g_cur[dv[e]], 1);
        __half2 h = __floats2half2_rn(s1[e], s2[e]);
        uint2 pk;
        pk.x = (unsigned)sv[e];
        pk.y = *reinterpret_cast<unsigned*>(&h);
        c_pack[pos] = pk;
    }
}

// ---------------- tensor-core GEMM ----------------
// internal input (useInternal=1) reads fp16 g_hB; external reads fp32.
template <int KD, int ATT>
__global__ void k_gemm(const float* __restrict__ Xext, const float* __restrict__ W,
                       const float* __restrict__ att_s, const float* __restrict__ att_d,
                       int useInternal) {
    __shared__ __half Xs[64][KD + 8];
    __shared__ __half Ws[KD][72];
    __shared__ float sred[64], dred[64];
    int tid = threadIdx.x;
    int node0 = blockIdx.x * 64;

    if (useInternal) {
        for (int i = tid; i < 64 * (KD / 2); i += 256) {
            int r = i / (KD / 2), c2 = i % (KD / 2);
            __half2 v = (node0 + r < NN)
                ? ((const __half2*)(g_hB + (size_t)(node0 + r) * KD))[c2]
                : __floats2half2_rn(0.f, 0.f);
            *((__half2*)&Xs[r][c2 * 2]) = v;
        }
    } else {
        for (int i = tid; i < 64 * KD; i += 256) {
            int r = i / KD, k = i % KD;
            float v = (node0 + r < NN) ? Xext[(size_t)(node0 + r) * KD + k] : 0.f;
            Xs[r][k] = __float2half(v);
        }
    }
    for (int i = tid; i < KD * 64; i += 256) {
        int k = i >> 6, n = i & 63;
        Ws[k][n] = __float2half(W[k * 64 + n]);
    }
    if (ATT && tid < 64) { sred[tid] = 0.f; dred[tid] = 0.f; }
    __syncthreads();

    int wid  = tid >> 5;
    int lane = tid & 31;
    int rt = wid >> 1;
    int ch = wid & 1;
    int g  = lane >> 2;
    int t2 = (lane & 3) * 2;
    int row0 = rt * 16;

    float c[4][4];
    #pragma unroll
    for (int nt = 0; nt < 4; nt++)
        #pragma unroll
        for (int q = 0; q < 4; q++) c[nt][q] = 0.f;

    #pragma unroll
    for (int ks = 0; ks < KD / 16; ks++) {
        int k0 = ks * 16;
        unsigned a0 = *(const unsigned*)&Xs[row0 + g    ][k0 + t2];
        unsigned a1 = *(const unsigned*)&Xs[row0 + g + 8][k0 + t2];
        unsigned a2 = *(const unsigned*)&Xs[row0 + g    ][k0 + t2 + 8];
        unsigned a3 = *(const unsigned*)&Xs[row0 + g + 8][k0 + t2 + 8];
        #pragma unroll
        for (int nt = 0; nt < 4; nt++) {
            int n0 = ch * 32 + nt * 8 + g;
            __half2 b0h = __halves2half2(Ws[k0 + t2    ][n0], Ws[k0 + t2 + 1][n0]);
            __half2 b1h = __halves2half2(Ws[k0 + t2 + 8][n0], Ws[k0 + t2 + 9][n0]);
            unsigned b0 = *reinterpret_cast<unsigned*>(&b0h);
            unsigned b1 = *reinterpret_cast<unsigned*>(&b1h);
            asm volatile(
                "mma.sync.aligned.m16n8k16.row.col.f32.f16.f16.f32 "
                "{%0,%1,%2,%3}, {%4,%5,%6,%7}, {%8,%9}, {%0,%1,%2,%3};"
                : "+f"(c[nt][0]), "+f"(c[nt][1]), "+f"(c[nt][2]), "+f"(c[nt][3])
                : "r"(a0), "r"(a1), "r"(a2), "r"(a3), "r"(b0), "r"(b1));
        }
    }

    int rowA = node0 + row0 + g;
    int rowB = rowA + 8;
    #pragma unroll
    for (int nt = 0; nt < 4; nt++) {
        int col = ch * 32 + nt * 8 + t2;
        if (rowA < NN)
            *(__half2*)&g_hw[(size_t)rowA * 64 + col] = __floats2half2_rn(c[nt][0], c[nt][1]);
        if (rowB < NN)
            *(__half2*)&g_hw[(size_t)rowB * 64 + col] = __floats2half2_rn(c[nt][2], c[nt][3]);
    }

    if (ATT) {
        float pAs = 0.f, pAd = 0.f, pBs = 0.f, pBd = 0.f;
        #pragma unroll
        for (int nt = 0; nt < 4; nt++) {
            int col = ch * 32 + nt * 8 + t2;
            float s0 = att_s[col], s1v = att_s[col + 1];
            float d0 = att_d[col], d1v = att_d[col + 1];
            pAs += c[nt][0] * s0 + c[nt][1] * s1v;
            pAd += c[nt][0] * d0 + c[nt][1] * d1v;
            pBs += c[nt][2] * s0 + c[nt][3] * s1v;
            pBd += c[nt][2] * d0 + c[nt][3] * d1v;
        }
        #pragma unroll
        for (int o = 1; o < 4; o <<= 1) {
            pAs += __shfl_xor_sync(0xffffffffu, pAs, o);
            pAd += __shfl_xor_sync(0xffffffffu, pAd, o);
            pBs += __shfl_xor_sync(0xffffffffu, pBs, o);
            pBd += __shfl_xor_sync(0xffffffffu, pBd, o);
        }
        if ((lane & 3) == 0) {
            atomicAdd(&sred[row0 + g],     pAs);
            atomicAdd(&dred[row0 + g],     pAd);
            atomicAdd(&sred[row0 + g + 8], pBs);
            atomicAdd(&dred[row0 + g + 8], pBd);
        }
        __syncthreads();
        if (tid < 64 && node0 + tid < NN) {
            g_as[node0 + tid] = sred[tid];
            g_ad[node0 + tid] = dred[tid];
        }
    }
}

// ---------------- gathers (R7 structure; OUT selects fp16 g_hB / fp32 g_hA) ----

__device__ __forceinline__ float2 hwrow(int s, int lane) {
    __half2 v = *((const __half2*)(g_hw + (size_t)s * 64) + lane);
    return __half22float2(v);
}

__global__ void k_gcn_node(const float* __restrict__ b) {
    int node = blockIdx.x * 8 + (threadIdx.x >> 5);
    int lane = threadIdx.x & 31;
    if (node >= NN) return;
    int rs = g_rs[node], re = g_rs[node + 1];
    float a0 = 0.f, a1 = 0.f;
    for (int jb = rs; jb < re; jb += 32) {
        int n = re - jb; if (n > 32) n = 32;
        int s_l = 0; float w_l = 0.f;
        if (lane < n) {
            s_l = (int)c_pack[jb + lane].x;
            w_l = g_dinv[s_l];
        }
        #pragma unroll 8
        for (int j = 0; j < n; j++) {
            int s   = __shfl_sync(0xffffffffu, s_l, j);
            float w = __shfl_sync(0xffffffffu, w_l, j);
            float2 f = hwrow(s, lane);
            a0 += w * f.x; a1 += w * f.y;
        }
    }
    float di = g_dinv[node];
    float2 fs = hwrow(node, lane);
    a0 += di * fs.x; a1 += di * fs.y;
    float2 bb = ((const float2*)b)[lane];
    float ox = fmaxf(a0 * di + bb.x, 0.f);
    float oy = fmaxf(a1 * di + bb.y, 0.f);
    ((__half2*)(g_hB + (size_t)node * 64))[lane] = __floats2half2_rn(ox, oy);
}

// OUT: 0 -> write fp16 g_hB (feeds next GEMM), 1 -> write fp32 g_hA (feeds pool)
template <int LAYER, int OUT>
__global__ void k_gat_node(const float* __restrict__ b) {
    int node = blockIdx.x * 8 + (threadIdx.x >> 5);
    int lane = threadIdx.x & 31;
    if (node >= NN) return;
    int rs = g_rs[node], re = g_rs[node + 1];
    float ad_n = g_ad[node];
    float a0 = 0.f, a1 = 0.f, den_l = 0.f, es_l = 0.f;
    for (int jb = rs; jb < re; jb += 32) {
        int n = re - jb; if (n > 32) n = 32;
        int s_l = 0; float x_l = 0.f;
        if (lane < n) {
            uint2 q = c_pack[jb + lane];
            s_l = (int)q.x;
            __half2 eh = *reinterpret_cast<__half2*>(&q.y);
            float e = (LAYER == 1) ? __low2float(eh) : __high2float(eh);
            x_l = __expf(lrelu(g_as[s_l] + ad_n + e));
            den_l += x_l;
            es_l  += e;
        }
        #pragma unroll 8
        for (int j = 0; j < n; j++) {
            int s   = __shfl_sync(0xffffffffu, s_l, j);
            float x = __shfl_sync(0xffffffffu, x_l, j);
            float2 f = hwrow(s, lane);
            a0 += x * f.x; a1 += x * f.y;
        }
    }
    #pragma unroll
    for (int o = 16; o; o >>= 1) {
        den_l += __shfl_xor_sync(0xffffffffu, den_l, o);
        es_l  += __shfl_xor_sync(0xffffffffu, es_l, o);
    }
    float cnt = (float)(re - rs);
    float x = __expf(lrelu(g_as[node] + ad_n + es_l / fmaxf(cnt, 1.f)));
    float den = den_l + x;
    float2 fs = hwrow(node, lane);
    a0 += x * fs.x; a1 += x * fs.y;
    float inv = 1.f / den;
    float2 bb = ((const float2*)b)[lane];
    float ox = fmaxf(a0 * inv + bb.x, 0.f);
    float oy = fmaxf(a1 * inv + bb.y, 0.f);
    if (OUT == 0) {
        ((__half2*)(g_hB + (size_t)node * 64))[lane] = __floats2half2_rn(ox, oy);
    } else {
        float2 o; o.x = ox; o.y = oy;
        ((float2*)(g_hA + (size_t)node * 64))[lane] = o;
    }
}

// ---------------- pool + head (R12-exact) ----------------

__global__ void k_pool(const int* __restrict__ batch) {
    int c   = threadIdx.x & 63;
    int grp = threadIdx.x >> 6;
    int n0  = blockIdx.x * 64 + grp * 16;
    if (n0 >= NN) return;
    int curg = batch[n0];
    float m = -3.402823466e+38f;
    for (int k = 0; k < 16; k++) {
        int n = n0 + k;
        if (n >= NN) break;
        int bg = batch[n];
        if (bg != curg) {
            atomicMax(&g_pool[curg * 64 + c], encf(m));
            m = -3.402823466e+38f;
            curg = bg;
        }
        m = fmaxf(m, g_hA[(size_t)n * 64 + c]);
    }
    atomicMax(&g_pool[curg * 64 + c], encf(m));
}

__global__ void k_fc(const float* __restrict__ W1, const float* __restrict__ b1,
                     const float* __restrict__ W2, const float* __restrict__ b2,
                     float* __restrict__ out) {
    __shared__ float t0[64], t1[64];
    int g = blockIdx.x, c = threadIdx.x;
    t0[c] = decf(g_pool[g * 64 + c]);
    g_pool[g * 64 + c] = ENC_NEGINF;
    __syncthreads();
    float s = 0.f;
    #pragma unroll 8
    for (int k = 0; k < 64; k++) s += t0[k] * W1[k * 64 + c];
    t1[c] = fmaxf(s + b1[c], 0.f);
    __syncthreads();
    float o = 0.f;
    #pragma unroll 8
    for (int k = 0; k < 64; k++) o += t1[k] * W2[k * 64 + c];
    out[g * 64 + c] = o + b2[c];
}

// ---------------- launch ----------------
extern "C" void kernel_launch(void* const* d_in, const int* in_sizes, int n_in,
                              void* d_out, int out_size) {
    const float* x     = (const float*)d_in[0];
    const int*   ei    = (const int*)  d_in[1];
    const float* ea    = (const float*)d_in[2];
    const int*   batch = (const int*)  d_in[3];
    const float* W_gcn = (const float*)d_in[4];
    const float* b_gcn = (const float*)d_in[5];
    const float* W1    = (const float*)d_in[6];
    const float* We1   = (const float*)d_in[7];
    const float* as1   = (const float*)d_in[8];
    const float* ad1   = (const float*)d_in[9];
    const float* ae1   = (const float*)d_in[10];
    const float* b1    = (const float*)d_in[11];
    const float* W2    = (const float*)d_in[12];
    const float* We2   = (const float*)d_in[13];
    const float* as2   = (const float*)d_in[14];
    const float* ad2   = (const float*)d_in[15];
    const float* ae2   = (const float*)d_in[16];
    const float* b2    = (const float*)d_in[17];
    const float* Wf1   = (const float*)d_in[18];
    const float* bf1   = (const float*)d_in[19];
    const float* Wf2   = (const float*)d_in[20];
    const float* bf2   = (const float*)d_in[21];
    float* out = (float*)d_out;

    const int* src = ei;
    const int* dst = ei + EE;

    const int TB = 256;
    const int gGemm = (NN + 63) / 64;
    const int gNode = (NN + 7) / 8;

    cudaStream_t s2;
    cudaEvent_t evA, evB;
    cudaStreamCreateWithFlags(&s2, cudaStreamNonBlocking);
    cudaEventCreateWithFlags(&evA, cudaEventDisableTiming);
    cudaEventCreateWithFlags(&evB, cudaEventDisableTiming);

    cudaEventRecord(evA, 0);
    cudaStreamWaitEvent(s2, evA, 0);
    k_gemm<128, 0><<<gGemm, TB, 0, s2>>>(x, W_gcn, nullptr, nullptr, 0);
    cudaEventRecord(evB, s2);

    k_cnt<<<(EE / 4 + TB - 1) / TB, TB>>>((const int4*)dst, We1, ae1, We2, ae2);
    k_scan1<<<SCAN_G, SCAN_B>>>();
    k_scan3<<<SCAN_G, SCAN_B>>>();
    k_scatter<<<(EE / 4 + TB - 1) / TB, TB>>>(ea, src, dst);

    cudaStreamWaitEvent(0, evB, 0);

    k_gcn_node<<<gNode, TB>>>(b_gcn);

    k_gemm<64, 1><<<gGemm, TB>>>(nullptr, W1, as1, ad1, 1);
    k_gat_node<1, 0><<<gNode, TB>>>(b1);

    k_gemm<64, 1><<<gGemm, TB>>>(nullptr, W2, as2, ad2, 1);
    k_gat_node<2, 1><<<gNode, TB>>>(b2);

    k_pool<<<(NN + 63) / 64, TB>>>(batch);
    k_fc<<<GG, 64>>>(Wf1, bf1, Wf2, bf2, out);

    cudaStreamDestroy(s2);
    cudaEventDestroy(evA);
    cudaEventDestroy(evB);
}

// round 14
// speedup vs baseline: 1.1184x; 1.0228x over previous
#include <cuda_runtime.h>
#include <cuda_fp16.h>

#define NN 100000
#define EE 1600000
#define GG 2048
#define HD 64
#define SCAN_B 1024
#define SCAN_G ((NN + SCAN_B - 1) / SCAN_B)   // 98

// ---------------- scratch ----------------
__device__ float    g_hA[NN * HD];      // fp32 final-layer activations (fc input)
__device__ __half   g_hB[NN * HD];      // fp16 inter-layer activations (GEMM input)
__device__ __half   g_hw[NN * HD];      // fp16 pre-aggregation features
__device__ float    g_dinv[NN];
__device__ float    g_as[NN], g_ad[NN];
__device__ int      g_cnt[NN];          // stays zeroed between runs
__device__ int      g_rs[NN + 1];
__device__ int      g_cur[NN];
__device__ int      g_bsum[SCAN_G], g_boff[SCAN_G];
__device__ int      g_tick;             // stays zeroed between runs
__device__ volatile int g_flag;         // release flag; reset by k_cnt each run
__device__ uint2    c_pack[EE];         // (src, half2(es1,es2)) CSR-ordered
__device__ float    g_v[32];

__device__ __forceinline__ float lrelu(float a) { return (a > 0.f) ? a : 0.2f * a; }

// ---------------- setup ----------------

__global__ void k_cnt(const int4* __restrict__ dst4,
                      const float* __restrict__ We1, const float* __restrict__ ae1,
                      const float* __restrict__ We2, const float* __restrict__ ae2) {
    int i = blockIdx.x * blockDim.x + threadIdx.x;
    if (blockIdx.x == 0 && threadIdx.x < 32) {
        int t = threadIdx.x;
        const float* We = (t < 16) ? We1 : We2;
        const float* ae = (t < 16) ? ae1 : ae2;
        int j = t & 15;
        float s = 0.f;
        #pragma unroll 8
        for (int c = 0; c < HD; c++) s += We[j * HD + c] * ae[c];
        g_v[t] = s;
    }
    if (blockIdx.x == 0 && threadIdx.x == 32) g_flag = 0;   // arm scan release
    if (i < EE / 4) {
        int4 d = dst4[i];
        atomicAdd(&g_cnt[d.x], 1);
        atomicAdd(&g_cnt[d.y], 1);
        atomicAdd(&g_cnt[d.z], 1);
        atomicAdd(&g_cnt[d.w], 1);
    }
}

// fused scan: warp-shuffle block scan -> last-block cross-scan -> spin -> finalize
// 98 blocks of 1024 thr <= 148 SMs * 2048 thr: all co-resident, spin is safe.
__global__ void k_scan() {
    __shared__ int wsum[32];
    __shared__ int is_last;
    int t = threadIdx.x;
    int i = blockIdx.x * SCAN_B + t;
    int v = (i < NN) ? g_cnt[i] : 0;
    int lane = t & 31, w = t >> 5;
    int x = v;
    #pragma unroll
    for (int off = 1; off < 32; off <<= 1) {
        int y = __shfl_up_sync(0xffffffffu, x, off);
        if (lane >= off) x += y;
    }
    if (lane == 31) wsum[w] = x;
    __syncthreads();
    if (w == 0) {
        int s = wsum[lane];
        #pragma unroll
        for (int off = 1; off < 32; off <<= 1) {
            int y = __shfl_up_sync(0xffffffffu, s, off);
            if (lane >= off) s += y;
        }
        wsum[lane] = s;
    }
    __syncthreads();
    int incl = x + ((w > 0) ? wsum[w - 1] : 0);
    if (t == SCAN_B - 1) g_bsum[blockIdx.x] = incl;
    __threadfence();
    __syncthreads();
    if (t == 0) is_last = (atomicAdd(&g_tick, 1) == SCAN_G - 1) ? 1 : 0;
    __syncthreads();
    if (is_last) {
        if (t < 32) {
            __threadfence();
            int base = lane * 4;
            int v0 = (base + 0 < SCAN_G) ? g_bsum[base + 0] : 0;
            int v1 = (base + 1 < SCAN_G) ? g_bsum[base + 1] : 0;
            int v2 = (base + 2 < SCAN_G) ? g_bsum[base + 2] : 0;
            int v3 = (base + 3 < SCAN_G) ? g_bsum[base + 3] : 0;
            int e1 = v0, e2 = v0 + v1, e3 = v0 + v1 + v2;
            int tot = e3 + v3;
            int xx = tot;
            #pragma unroll
            for (int off = 1; off < 32; off <<= 1) {
                int y = __shfl_up_sync(0xffffffffu, xx, off);
                if (lane >= off) xx += y;
            }
            int excl = xx - tot;
            if (base + 0 < SCAN_G) g_boff[base + 0] = excl;
            if (base + 1 < SCAN_G) g_boff[base + 1] = excl + e1;
            if (base + 2 < SCAN_G) g_boff[base + 2] = excl + e2;
            if (base + 3 < SCAN_G) g_boff[base + 3] = excl + e3;
            __threadfence();
            if (lane == 0) { g_tick = 0; g_flag = 1; }
        }
        __syncthreads();
    } else {
        if (t == 0) { while (g_flag == 0) { } }
        __syncthreads();
        __threadfence();
    }
    // finalize in place (uses locally-held incl/v; no g_rs re-read)
    if (i < NN) {
        int rs = incl - v + g_boff[blockIdx.x];
        g_rs[i] = rs;
        g_cur[i] = rs;
        g_dinv[i] = rsqrtf((float)(v + 1));
        g_cnt[i] = 0;
    }
    if (i == 0) g_rs[NN] = EE;
}

// 4 edges/thread scatter (R13)
__global__ void k_scatter(const float* __restrict__ ea,
                          const int* __restrict__ src, const int* __restrict__ dst) {
    int i = blockIdx.x * blockDim.x + threadIdx.x;
    const int Q = EE / 4;
    if (i >= Q) return;
    float s1[4], s2[4];
    int sv[4], dv[4];
    #pragma unroll
    for (int e = 0; e < 4; e++) {
        int idx = i + e * Q;
        sv[e] = src[idx];
        dv[e] = dst[idx];
        const float4* p = (const float4*)(ea + (size_t)idx * 16);
        float a1 = 0.f, a2 = 0.f;
        #pragma unroll
        for (int k = 0; k < 4; k++) {
            float4 q = p[k];
            a1 += q.x * g_v[4*k] + q.y * g_v[4*k+1] + q.z * g_v[4*k+2] + q.w * g_v[4*k+3];
            a2 += q.x * g_v[16+4*k] + q.y * g_v[16+4*k+1] + q.z * g_v[16+4*k+2] + q.w * g_v[16+4*k+3];
        }
        s1[e] = a1; s2[e] = a2;
    }
    #pragma unroll
    for (int e = 0; e < 4; e++) {
        int pos = atomicAdd(&g_cur[dv[e]], 1);
        __half2 h = __floats2half2_rn(s1[e], s2[e]);
        uint2 pk;
        pk.x = (unsigned)sv[e];
        pk.y = *reinterpret_cast<unsigned*>(&h);
        c_pack[pos] = pk;
    }
}

// ---------------- tensor-core GEMM (R13) ----------------
template <int KD, int ATT>
__global__ void k_gemm(const float* __restrict__ Xext, const float* __restrict__ W,
                       const float* __restrict__ att_s, const float* __restrict__ att_d,
                       int useInternal) {
    __shared__ __half Xs[64][KD + 8];
    __shared__ __half Ws[KD][72];
    __shared__ float sred[64], dred[64];
    int tid = threadIdx.x;
    int node0 = blockIdx.x * 64;

    if (useInternal) {
        for (int i = tid; i < 64 * (KD / 2); i += 256) {
            int r = i / (KD / 2), c2 = i % (KD / 2);
            __half2 v = (node0 + r < NN)
                ? ((const __half2*)(g_hB + (size_t)(node0 + r) * KD))[c2]
                : __floats2half2_rn(0.f, 0.f);
            *((__half2*)&Xs[r][c2 * 2]) = v;
        }
    } else {
        for (int i = tid; i < 64 * KD; i += 256) {
            int r = i / KD, k = i % KD;
            float v = (node0 + r < NN) ? Xext[(size_t)(node0 + r) * KD + k] : 0.f;
            Xs[r][k] = __float2half(v);
        }
    }
    for (int i = tid; i < KD * 64; i += 256) {
        int k = i >> 6, n = i & 63;
        Ws[k][n] = __float2half(W[k * 64 + n]);
    }
    if (ATT && tid < 64) { sred[tid] = 0.f; dred[tid] = 0.f; }
    __syncthreads();

    int wid  = tid >> 5;
    int lane = tid & 31;
    int rt = wid >> 1;
    int ch = wid & 1;
    int g  = lane >> 2;
    int t2 = (lane & 3) * 2;
    int row0 = rt * 16;

    float c[4][4];
    #pragma unroll
    for (int nt = 0; nt < 4; nt++)
        #pragma unroll
        for (int q = 0; q < 4; q++) c[nt][q] = 0.f;

    #pragma unroll
    for (int ks = 0; ks < KD / 16; ks++) {
        int k0 = ks * 16;
        unsigned a0 = *(const unsigned*)&Xs[row0 + g    ][k0 + t2];
        unsigned a1 = *(const unsigned*)&Xs[row0 + g + 8][k0 + t2];
        unsigned a2 = *(const unsigned*)&Xs[row0 + g    ][k0 + t2 + 8];
        unsigned a3 = *(const unsigned*)&Xs[row0 + g + 8][k0 + t2 + 8];
        #pragma unroll
        for (int nt = 0; nt < 4; nt++) {
            int n0 = ch * 32 + nt * 8 + g;
            __half2 b0h = __halves2half2(Ws[k0 + t2    ][n0], Ws[k0 + t2 + 1][n0]);
            __half2 b1h = __halves2half2(Ws[k0 + t2 + 8][n0], Ws[k0 + t2 + 9][n0]);
            unsigned b0 = *reinterpret_cast<unsigned*>(&b0h);
            unsigned b1 = *reinterpret_cast<unsigned*>(&b1h);
            asm volatile(
                "mma.sync.aligned.m16n8k16.row.col.f32.f16.f16.f32 "
                "{%0,%1,%2,%3}, {%4,%5,%6,%7}, {%8,%9}, {%0,%1,%2,%3};"
                : "+f"(c[nt][0]), "+f"(c[nt][1]), "+f"(c[nt][2]), "+f"(c[nt][3])
                : "r"(a0), "r"(a1), "r"(a2), "r"(a3), "r"(b0), "r"(b1));
        }
    }

    int rowA = node0 + row0 + g;
    int rowB = rowA + 8;
    #pragma unroll
    for (int nt = 0; nt < 4; nt++) {
        int col = ch * 32 + nt * 8 + t2;
        if (rowA < NN)
            *(__half2*)&g_hw[(size_t)rowA * 64 + col] = __floats2half2_rn(c[nt][0], c[nt][1]);
        if (rowB < NN)
            *(__half2*)&g_hw[(size_t)rowB * 64 + col] = __floats2half2_rn(c[nt][2], c[nt][3]);
    }

    if (ATT) {
        float pAs = 0.f, pAd = 0.f, pBs = 0.f, pBd = 0.f;
        #pragma unroll
        for (int nt = 0; nt < 4; nt++) {
            int col = ch * 32 + nt * 8 + t2;
            float s0 = att_s[col], s1v = att_s[col + 1];
            float d0 = att_d[col], d1v = att_d[col + 1];
            pAs += c[nt][0] * s0 + c[nt][1] * s1v;
            pAd += c[nt][0] * d0 + c[nt][1] * d1v;
            pBs += c[nt][2] * s0 + c[nt][3] * s1v;
            pBd += c[nt][2] * d0 + c[nt][3] * d1v;
        }
        #pragma unroll
        for (int o = 1; o < 4; o <<= 1) {
            pAs += __shfl_xor_sync(0xffffffffu, pAs, o);
            pAd += __shfl_xor_sync(0xffffffffu, pAd, o);
            pBs += __shfl_xor_sync(0xffffffffu, pBs, o);
            pBd += __shfl_xor_sync(0xffffffffu, pBd, o);
        }
        if ((lane & 3) == 0) {
            atomicAdd(&sred[row0 + g],     pAs);
            atomicAdd(&dred[row0 + g],     pAd);
            atomicAdd(&sred[row0 + g + 8], pBs);
            atomicAdd(&dred[row0 + g + 8], pBd);
        }
        __syncthreads();
        if (tid < 64 && node0 + tid < NN) {
            g_as[node0 + tid] = sred[tid];
            g_ad[node0 + tid] = dred[tid];
        }
    }
}

// ---------------- gathers (R13) ----------------

__device__ __forceinline__ float2 hwrow(int s, int lane) {
    __half2 v = *((const __half2*)(g_hw + (size_t)s * 64) + lane);
    return __half22float2(v);
}

__global__ void k_gcn_node(const float* __restrict__ b) {
    int node = blockIdx.x * 8 + (threadIdx.x >> 5);
    int lane = threadIdx.x & 31;
    if (node >= NN) return;
    int rs = g_rs[node], re = g_rs[node + 1];
    float a0 = 0.f, a1 = 0.f;
    for (int jb = rs; jb < re; jb += 32) {
        int n = re - jb; if (n > 32) n = 32;
        int s_l = 0; float w_l = 0.f;
        if (lane < n) {
            s_l = (int)c_pack[jb + lane].x;
            w_l = g_dinv[s_l];
        }
        #pragma unroll 8
        for (int j = 0; j < n; j++) {
            int s   = __shfl_sync(0xffffffffu, s_l, j);
            float w = __shfl_sync(0xffffffffu, w_l, j);
            float2 f = hwrow(s, lane);
            a0 += w * f.x; a1 += w * f.y;
        }
    }
    float di = g_dinv[node];
    float2 fs = hwrow(node, lane);
    a0 += di * fs.x; a1 += di * fs.y;
    float2 bb = ((const float2*)b)[lane];
    float ox = fmaxf(a0 * di + bb.x, 0.f);
    float oy = fmaxf(a1 * di + bb.y, 0.f);
    ((__half2*)(g_hB + (size_t)node * 64))[lane] = __floats2half2_rn(ox, oy);
}

// OUT: 0 -> fp16 g_hB (feeds next GEMM), 1 -> fp32 g_hA (feeds fc/pool)
template <int LAYER, int OUT>
__global__ void k_gat_node(const float* __restrict__ b) {
    int node = blockIdx.x * 8 + (threadIdx.x >> 5);
    int lane = threadIdx.x & 31;
    if (node >= NN) return;
    int rs = g_rs[node], re = g_rs[node + 1];
    float ad_n = g_ad[node];
    float a0 = 0.f, a1 = 0.f, den_l = 0.f, es_l = 0.f;
    for (int jb = rs; jb < re; jb += 32) {
        int n = re - jb; if (n > 32) n = 32;
        int s_l = 0; float x_l = 0.f;
        if (lane < n) {
            uint2 q = c_pack[jb + lane];
            s_l = (int)q.x;
            __half2 eh = *reinterpret_cast<__half2*>(&q.y);
            float e = (LAYER == 1) ? __low2float(eh) : __high2float(eh);
            x_l = __expf(lrelu(g_as[s_l] + ad_n + e));
            den_l += x_l;
            es_l  += e;
        }
        #pragma unroll 8
        for (int j = 0; j < n; j++) {
            int s   = __shfl_sync(0xffffffffu, s_l, j);
            float x = __shfl_sync(0xffffffffu, x_l, j);
            float2 f = hwrow(s, lane);
            a0 += x * f.x; a1 += x * f.y;
        }
    }
    #pragma unroll
    for (int o = 16; o; o >>= 1) {
        den_l += __shfl_xor_sync(0xffffffffu, den_l, o);
        es_l  += __shfl_xor_sync(0xffffffffu, es_l, o);
    }
    float cnt = (float)(re - rs);
    float x = __expf(lrelu(g_as[node] + ad_n + es_l / fmaxf(cnt, 1.f)));
    float den = den_l + x;
    float2 fs = hwrow(node, lane);
    a0 += x * fs.x; a1 += x * fs.y;
    float inv = 1.f / den;
    float2 bb = ((const float2*)b)[lane];
    float ox = fmaxf(a0 * inv + bb.x, 0.f);
    float oy = fmaxf(a1 * inv + bb.y, 0.f);
    if (OUT == 0) {
        ((__half2*)(g_hB + (size_t)node * 64))[lane] = __floats2half2_rn(ox, oy);
    } else {
        float2 o; o.x = ox; o.y = oy;
        ((float2*)(g_hA + (size_t)node * 64))[lane] = o;
    }
}

// ---------------- head: pool (by node range via binary search) + 2-layer MLP ----

__global__ void k_fc(const int* __restrict__ batch,
                     const float* __restrict__ W1, const float* __restrict__ b1,
                     const float* __restrict__ W2, const float* __restrict__ b2,
                     float* __restrict__ out) {
    __shared__ float t0[64], t1[64];
    __shared__ int srange[2];
    int g = blockIdx.x, c = threadIdx.x;
    if (c < 2) {
        int target = g + c;           // lower_bound(batch, g) and lower_bound(batch, g+1)
        int lo = 0, hi = NN;
        while (lo < hi) {
            int mid = (lo + hi) >> 1;
            if (batch[mid] < target) lo = mid + 1; else hi = mid;
        }
        srange[c] = lo;
    }
    __syncthreads();
    int ns = srange[0], ne = srange[1];
    float m = -3.402823466e+38f;
    for (int n = ns; n < ne; n++)
        m = fmaxf(m, g_hA[(size_t)n * 64 + c]);
    t0[c] = m;
    __syncthreads();
    float s = 0.f;
    #pragma unroll 8
    for (int k = 0; k < 64; k++) s += t0[k] * W1[k * 64 + c];
    t1[c] = fmaxf(s + b1[c], 0.f);
    __syncthreads();
    float o = 0.f;
    #pragma unroll 8
    for (int k = 0; k < 64; k++) o += t1[k] * W2[k * 64 + c];
    out[g * 64 + c] = o + b2[c];
}

// ---------------- launch ----------------
extern "C" void kernel_launch(void* const* d_in, const int* in_sizes, int n_in,
                              void* d_out, int out_size) {
    const float* x     = (const float*)d_in[0];
    const int*   ei    = (const int*)  d_in[1];
    const float* ea    = (const float*)d_in[2];
    const int*   batch = (const int*)  d_in[3];
    const float* W_gcn = (const float*)d_in[4];
    const float* b_gcn = (const float*)d_in[5];
    const float* W1    = (const float*)d_in[6];
    const float* We1   = (const float*)d_in[7];
    const float* as1   = (const float*)d_in[8];
    const float* ad1   = (const float*)d_in[9];
    const float* ae1   = (const float*)d_in[10];
    const float* b1    = (const float*)d_in[11];
    const float* W2    = (const float*)d_in[12];
    const float* We2   = (const float*)d_in[13];
    const float* as2   = (const float*)d_in[14];
    const float* ad2   = (const float*)d_in[15];
    const float* ae2   = (const float*)d_in[16];
    const float* b2    = (const float*)d_in[17];
    const float* Wf1   = (const float*)d_in[18];
    const float* bf1   = (const float*)d_in[19];
    const float* Wf2   = (const float*)d_in[20];
    const float* bf2   = (const float*)d_in[21];
    float* out = (float*)d_out;

    const int* src = ei;
    const int* dst = ei + EE;

    const int TB = 256;
    const int gGemm = (NN + 63) / 64;
    const int gNode = (NN + 7) / 8;

    cudaStream_t s2;
    cudaEvent_t evA, evB;
    cudaStreamCreateWithFlags(&s2, cudaStreamNonBlocking);
    cudaEventCreateWithFlags(&evA, cudaEventDisableTiming);
    cudaEventCreateWithFlags(&evB, cudaEventDisableTiming);

    cudaEventRecord(evA, 0);
    cudaStreamWaitEvent(s2, evA, 0);
    k_gemm<128, 0><<<gGemm, TB, 0, s2>>>(x, W_gcn, nullptr, nullptr, 0);
    cudaEventRecord(evB, s2);

    k_cnt<<<(EE / 4 + TB - 1) / TB, TB>>>((const int4*)dst, We1, ae1, We2, ae2);
    k_scan<<<SCAN_G, SCAN_B>>>();
    k_scatter<<<(EE / 4 + TB - 1) / TB, TB>>>(ea, src, dst);

    cudaStreamWaitEvent(0, evB, 0);

    k_gcn_node<<<gNode, TB>>>(b_gcn);

    k_gemm<64, 1><<<gGemm, TB>>>(nullptr, W1, as1, ad1, 1);
    k_gat_node<1, 0><<<gNode, TB>>>(b1);

    k_gemm<64, 1><<<gGemm, TB>>>(nullptr, W2, as2, ad2, 1);
    k_gat_node<2, 1><<<gNode, TB>>>(b2);

    k_fc<<<GG, 64>>>(batch, Wf1, bf1, Wf2, bf2, out);

    cudaStreamDestroy(s2);
    cudaEventDestroy(evA);
    cudaEventDestroy(evB);
}